// round 2
// baseline (speedup 1.0000x reference)
#include <cuda_runtime.h>
#include <cstdint>

// ---------------------------------------------------------------------------
// DNNLSTMWithAttention — algebraically reduced:
//   Y[B,512] = x @ Wb.T          (Wb = [fc1_w ; W_ih(i) ; W_ih(g) ; W_ih(o)][:, :512])
//   d1 = relu(Y[:, :128] + fc1_b)
//   d2 = relu(d1 @ fc2_w.T + fc2_b)
//   d3 = d2 @ fc3_w.T + fc3_b
//   i  = Y[:,128:256] + d3 @ Wih_i[:,512:].T + b_i
//   g  = Y[:,256:384] + d3 @ Wih_g[:,512:].T + b_g
//   o  = Y[:,384:512] + d3 @ Wih_o[:,512:].T + b_o
//   c = sig(i)*tanh(g); h = sig(o)*tanh(c)     (f gate & W_hh unused; attention == identity)
//   out = h @ fc_w.T + fc_b
// All GEMMs via tf32 mma.sync (fp32 accumulate) for <1e-3 accuracy.
// ---------------------------------------------------------------------------

#define NROWS 131072
#define P2 132  // smem pitch (words) for kernel-2 buffers

__device__ float    g_Y[(size_t)NROWS * 512]; // 268 MB scratch
__device__ uint32_t g_Wb[512 * 512];          // packed tf32 big-GEMM weights

__device__ __forceinline__ uint32_t tf32cvt(float f) {
    uint32_t r;
    asm("cvt.rna.tf32.f32 %0, %1;" : "=r"(r) : "f"(f));
    return r;
}

__device__ __forceinline__ void mma8(float* c, const uint32_t* a, uint32_t b0, uint32_t b1) {
    asm volatile(
        "mma.sync.aligned.m16n8k8.row.col.f32.tf32.tf32.f32 "
        "{%0,%1,%2,%3},{%4,%5,%6,%7},{%8,%9},{%0,%1,%2,%3};"
        : "+f"(c[0]), "+f"(c[1]), "+f"(c[2]), "+f"(c[3])
        : "r"(a[0]), "r"(a[1]), "r"(a[2]), "r"(a[3]), "r"(b0), "r"(b1));
}

__device__ __forceinline__ float sigm(float x) { return 1.0f / (1.0f + expf(-x)); }

// ---------------------------------------------------------------------------
// Kernel 0: pack Wb[512][512] (tf32) from fc1_w and W_ih (skip f-gate rows).
// ---------------------------------------------------------------------------
__global__ void pack_wb_kernel(const float* __restrict__ fc1_w,
                               const float* __restrict__ W_ih) {
    int idx = blockIdx.x * 256 + threadIdx.x;   // 512*512 = 262144 threads total
    int r = idx >> 9;
    int k = idx & 511;
    float v;
    if (r < 128) {
        v = fc1_w[r * 512 + k];
    } else {
        int sr = (r < 256) ? (r - 128) : r;     // i rows 0..127 ; g rows 256..383 ; o rows 384..511
        v = W_ih[(size_t)sr * 640 + k];
    }
    g_Wb[idx] = tf32cvt(v);
}

// ---------------------------------------------------------------------------
// Kernel 1: Y = x @ Wb.T   (M=131072, N=512, K=512)   BM=BN=128, BK=32
// ---------------------------------------------------------------------------
__global__ __launch_bounds__(256) void gemm1_kernel(const float* __restrict__ x) {
    __shared__ uint32_t sA[128][36];
    __shared__ uint32_t sB[128][36];

    const int tid  = threadIdx.x;
    const int lane = tid & 31;
    const int warp = tid >> 5;
    const int wm = warp >> 1;          // 0..3  (M)
    const int wn = warp & 1;           // 0..1  (N)
    const int g  = lane >> 2;
    const int t4 = lane & 3;

    const int mt = blockIdx.x;         // 0..1023
    const int nt = blockIdx.y;         // 0..3

    const float*    xg = x    + (size_t)mt * 128 * 512;
    const uint32_t* wg = g_Wb + (size_t)nt * 128 * 512;

    float acc[2][8][4];
#pragma unroll
    for (int mi = 0; mi < 2; mi++)
#pragma unroll
        for (int ni = 0; ni < 8; ni++)
#pragma unroll
            for (int e = 0; e < 4; e++) acc[mi][ni][e] = 0.0f;

    const int lr = tid >> 3;           // 0..31
    const int lc = (tid & 7) << 2;     // 0,4,...,28

    for (int k0 = 0; k0 < 512; k0 += 32) {
#pragma unroll
        for (int i = 0; i < 4; i++) {
            const float4 v = *reinterpret_cast<const float4*>(
                xg + (size_t)(lr + 32 * i) * 512 + k0 + lc);
            uint4 u;
            u.x = tf32cvt(v.x); u.y = tf32cvt(v.y);
            u.z = tf32cvt(v.z); u.w = tf32cvt(v.w);
            *reinterpret_cast<uint4*>(&sA[lr + 32 * i][lc]) = u;
            const uint4 w = *reinterpret_cast<const uint4*>(
                wg + (size_t)(lr + 32 * i) * 512 + k0 + lc);
            *reinterpret_cast<uint4*>(&sB[lr + 32 * i][lc]) = w;
        }
        __syncthreads();

#pragma unroll
        for (int kk = 0; kk < 32; kk += 8) {
            uint32_t a[2][4];
#pragma unroll
            for (int mi = 0; mi < 2; mi++) {
                int r = wm * 32 + mi * 16 + g;
                a[mi][0] = sA[r][kk + t4];
                a[mi][1] = sA[r + 8][kk + t4];
                a[mi][2] = sA[r][kk + t4 + 4];
                a[mi][3] = sA[r + 8][kk + t4 + 4];
            }
#pragma unroll
            for (int ni = 0; ni < 8; ni++) {
                int c = wn * 64 + ni * 8 + g;
                uint32_t b0 = sB[c][kk + t4];
                uint32_t b1 = sB[c][kk + t4 + 4];
                mma8(acc[0][ni], a[0], b0, b1);
                mma8(acc[1][ni], a[1], b0, b1);
            }
        }
        __syncthreads();
    }

    float* Yg = g_Y + (size_t)mt * 128 * 512 + nt * 128;
#pragma unroll
    for (int mi = 0; mi < 2; mi++)
#pragma unroll
        for (int ni = 0; ni < 8; ni++) {
            int r = wm * 32 + mi * 16 + g;
            int c = wn * 64 + ni * 8 + t4 * 2;
            *reinterpret_cast<float2*>(Yg + (size_t)r * 512 + c) =
                make_float2(acc[mi][ni][0], acc[mi][ni][1]);
            *reinterpret_cast<float2*>(Yg + (size_t)(r + 8) * 512 + c) =
                make_float2(acc[mi][ni][2], acc[mi][ni][3]);
        }
}

// ---------------------------------------------------------------------------
// tile GEMM on smem tf32 operands: C[128 x (NT*16)] += A[128 x KDIM] @ W.T
// warp layout: wm in 0..3 (32 rows each), wn in 0..1 (NT*8 cols each)
// ---------------------------------------------------------------------------
template <int KDIM, int NT>
__device__ __forceinline__ void tile_gemm(const uint32_t* __restrict__ sA,
                                          const uint32_t* __restrict__ sW,
                                          float acc[2][NT][4],
                                          int wm, int wn, int g, int t4) {
#pragma unroll
    for (int kk = 0; kk < KDIM; kk += 8) {
        uint32_t a[2][4];
#pragma unroll
        for (int mi = 0; mi < 2; mi++) {
            int r = wm * 32 + mi * 16 + g;
            a[mi][0] = sA[r * P2 + kk + t4];
            a[mi][1] = sA[(r + 8) * P2 + kk + t4];
            a[mi][2] = sA[r * P2 + kk + t4 + 4];
            a[mi][3] = sA[(r + 8) * P2 + kk + t4 + 4];
        }
#pragma unroll
        for (int ni = 0; ni < NT; ni++) {
            int n = (wn * NT + ni) * 8 + g;
            uint32_t b0 = sW[n * P2 + kk + t4];
            uint32_t b1 = sW[n * P2 + kk + t4 + 4];
            mma8(acc[0][ni], a[0], b0, b1);
            mma8(acc[1][ni], a[1], b0, b1);
        }
    }
}

// ---------------------------------------------------------------------------
// Kernel 2: fused tail. One CTA = 128 rows. 3 smem buffers (pitch P2).
// ---------------------------------------------------------------------------
__global__ __launch_bounds__(256) void tail_kernel(
    const float* __restrict__ fc1_b, const float* __restrict__ fc2_w,
    const float* __restrict__ fc2_b, const float* __restrict__ fc3_w,
    const float* __restrict__ fc3_b, const float* __restrict__ W_ih,
    const float* __restrict__ b_ih,  const float* __restrict__ b_hh,
    const float* __restrict__ fc_w,  const float* __restrict__ fc_b,
    float* __restrict__ out) {
    extern __shared__ uint32_t sm[];
    uint32_t* B0 = sm;                 // A-chain (d1 -> d3)
    uint32_t* B1 = sm + 128 * P2;      // weights
    uint32_t* B2 = sm + 2 * 128 * P2;  // staging (d2, i, c, h)
    float* B2f = reinterpret_cast<float*>(B2);

    const int tid  = threadIdx.x;
    const int lane = tid & 31;
    const int warp = tid >> 5;
    const int wm = warp >> 1;
    const int wn = warp & 1;
    const int g  = lane >> 2;
    const int t4 = lane & 3;

    const size_t rowbase = (size_t)blockIdx.x * 128;
    const float* Yg = g_Y + rowbase * 512;

    // ---- Stage 0: d1 = relu(Y[:, :128] + fc1_b) -> B0 ; load fc2_w -> B1 ----
    for (int i = tid; i < 128 * 32; i += 256) {
        int r = i >> 5, c4 = (i & 31) << 2;
        float4 v = *reinterpret_cast<const float4*>(Yg + (size_t)r * 512 + c4);
        float4 b = *reinterpret_cast<const float4*>(fc1_b + c4);
        uint4 u;
        u.x = tf32cvt(fmaxf(v.x + b.x, 0.0f));
        u.y = tf32cvt(fmaxf(v.y + b.y, 0.0f));
        u.z = tf32cvt(fmaxf(v.z + b.z, 0.0f));
        u.w = tf32cvt(fmaxf(v.w + b.w, 0.0f));
        *reinterpret_cast<uint4*>(&B0[r * P2 + c4]) = u;
    }
    for (int i = tid; i < 64 * 32; i += 256) {
        int r = i >> 5, c4 = (i & 31) << 2;
        float4 v = *reinterpret_cast<const float4*>(fc2_w + r * 128 + c4);
        uint4 u; u.x = tf32cvt(v.x); u.y = tf32cvt(v.y); u.z = tf32cvt(v.z); u.w = tf32cvt(v.w);
        *reinterpret_cast<uint4*>(&B1[r * P2 + c4]) = u;
    }
    __syncthreads();

    // ---- G1: d2 = relu(d1 @ fc2_w.T + fc2_b)  (K=128, N=64) -> B2 ----
    {
        float acc[2][4][4];
#pragma unroll
        for (int mi = 0; mi < 2; mi++)
#pragma unroll
            for (int ni = 0; ni < 4; ni++)
#pragma unroll
                for (int e = 0; e < 4; e++) acc[mi][ni][e] = 0.0f;
        tile_gemm<128, 4>(B0, B1, acc, wm, wn, g, t4);
#pragma unroll
        for (int mi = 0; mi < 2; mi++)
#pragma unroll
            for (int ni = 0; ni < 4; ni++) {
                int r0 = wm * 32 + mi * 16 + g;
                int c0 = (wn * 4 + ni) * 8 + t4 * 2;
                B2[r0 * P2 + c0]       = tf32cvt(fmaxf(acc[mi][ni][0] + fc2_b[c0], 0.0f));
                B2[r0 * P2 + c0 + 1]   = tf32cvt(fmaxf(acc[mi][ni][1] + fc2_b[c0 + 1], 0.0f));
                B2[(r0 + 8) * P2 + c0]     = tf32cvt(fmaxf(acc[mi][ni][2] + fc2_b[c0], 0.0f));
                B2[(r0 + 8) * P2 + c0 + 1] = tf32cvt(fmaxf(acc[mi][ni][3] + fc2_b[c0 + 1], 0.0f));
            }
    }
    __syncthreads();

    // ---- load fc3_w (128x64) -> B1 ----
    for (int i = tid; i < 128 * 16; i += 256) {
        int r = i >> 4, c4 = (i & 15) << 2;
        float4 v = *reinterpret_cast<const float4*>(fc3_w + r * 64 + c4);
        uint4 u; u.x = tf32cvt(v.x); u.y = tf32cvt(v.y); u.z = tf32cvt(v.z); u.w = tf32cvt(v.w);
        *reinterpret_cast<uint4*>(&B1[r * P2 + c4]) = u;
    }
    __syncthreads();

    // ---- G2: d3 = d2 @ fc3_w.T + fc3_b  (K=64, N=128) -> B0 ----
    {
        float acc[2][8][4];
#pragma unroll
        for (int mi = 0; mi < 2; mi++)
#pragma unroll
            for (int ni = 0; ni < 8; ni++)
#pragma unroll
                for (int e = 0; e < 4; e++) acc[mi][ni][e] = 0.0f;
        tile_gemm<64, 8>(B2, B1, acc, wm, wn, g, t4);
#pragma unroll
        for (int mi = 0; mi < 2; mi++)
#pragma unroll
            for (int ni = 0; ni < 8; ni++) {
                int r0 = wm * 32 + mi * 16 + g;
                int c0 = (wn * 8 + ni) * 8 + t4 * 2;
                B0[r0 * P2 + c0]       = tf32cvt(acc[mi][ni][0] + fc3_b[c0]);
                B0[r0 * P2 + c0 + 1]   = tf32cvt(acc[mi][ni][1] + fc3_b[c0 + 1]);
                B0[(r0 + 8) * P2 + c0]     = tf32cvt(acc[mi][ni][2] + fc3_b[c0]);
                B0[(r0 + 8) * P2 + c0 + 1] = tf32cvt(acc[mi][ni][3] + fc3_b[c0 + 1]);
            }
    }
    __syncthreads();

    // ---- Gates: i, g, o (each K=128, N=128, A = d3 in B0) ----
#pragma unroll 1
    for (int blk = 0; blk < 3; blk++) {
        const int wrow  = (blk == 0) ? 0 : (blk == 1) ? 256 : 384;  // W_ih row base
        const int bbase = wrow;                                     // bias index base
        const int ycol  = 128 + blk * 128;                          // Y column base

        for (int i = tid; i < 128 * 32; i += 256) {
            int r = i >> 5, c4 = (i & 31) << 2;
            float4 v = *reinterpret_cast<const float4*>(
                W_ih + (size_t)(wrow + r) * 640 + 512 + c4);
            uint4 u; u.x = tf32cvt(v.x); u.y = tf32cvt(v.y); u.z = tf32cvt(v.z); u.w = tf32cvt(v.w);
            *reinterpret_cast<uint4*>(&B1[r * P2 + c4]) = u;
        }
        __syncthreads();

        float acc[2][8][4];
#pragma unroll
        for (int mi = 0; mi < 2; mi++)
#pragma unroll
            for (int ni = 0; ni < 8; ni++)
#pragma unroll
                for (int e = 0; e < 4; e++) acc[mi][ni][e] = 0.0f;
        tile_gemm<128, 8>(B0, B1, acc, wm, wn, g, t4);

#pragma unroll
        for (int mi = 0; mi < 2; mi++)
#pragma unroll
            for (int ni = 0; ni < 8; ni++)
#pragma unroll
                for (int e = 0; e < 4; e++) {
                    int r = wm * 32 + mi * 16 + g + ((e >> 1) ? 8 : 0);
                    int c = (wn * 8 + ni) * 8 + t4 * 2 + (e & 1);
                    float val = acc[mi][ni][e] + Yg[(size_t)r * 512 + ycol + c] +
                                b_ih[bbase + c] + b_hh[bbase + c];
                    if (blk == 0) {
                        B2f[r * P2 + c] = val;                       // i (pre-act)
                    } else if (blk == 1) {
                        float iv = B2f[r * P2 + c];
                        B2f[r * P2 + c] = sigm(iv) * tanhf(val);     // c
                    } else {
                        float cv = B2f[r * P2 + c];
                        B2[r * P2 + c] = tf32cvt(sigm(val) * tanhf(cv));  // h (tf32)
                    }
                }
        __syncthreads();
    }

    // ---- load fc_w (128x128) -> B1 ----
    for (int i = tid; i < 128 * 32; i += 256) {
        int r = i >> 5, c4 = (i & 31) << 2;
        float4 v = *reinterpret_cast<const float4*>(fc_w + r * 128 + c4);
        uint4 u; u.x = tf32cvt(v.x); u.y = tf32cvt(v.y); u.z = tf32cvt(v.z); u.w = tf32cvt(v.w);
        *reinterpret_cast<uint4*>(&B1[r * P2 + c4]) = u;
    }
    __syncthreads();

    // ---- G4: out = h @ fc_w.T + fc_b  (K=128, N=128) -> global ----
    {
        float acc[2][8][4];
#pragma unroll
        for (int mi = 0; mi < 2; mi++)
#pragma unroll
            for (int ni = 0; ni < 8; ni++)
#pragma unroll
                for (int e = 0; e < 4; e++) acc[mi][ni][e] = 0.0f;
        tile_gemm<128, 8>(B2, B1, acc, wm, wn, g, t4);
#pragma unroll
        for (int mi = 0; mi < 2; mi++)
#pragma unroll
            for (int ni = 0; ni < 8; ni++) {
                int r0 = wm * 32 + mi * 16 + g;
                int c0 = (wn * 8 + ni) * 8 + t4 * 2;
                *reinterpret_cast<float2*>(out + (rowbase + r0) * 128 + c0) =
                    make_float2(acc[mi][ni][0] + fc_b[c0], acc[mi][ni][1] + fc_b[c0 + 1]);
                *reinterpret_cast<float2*>(out + (rowbase + r0 + 8) * 128 + c0) =
                    make_float2(acc[mi][ni][2] + fc_b[c0], acc[mi][ni][3] + fc_b[c0 + 1]);
            }
    }
}

// ---------------------------------------------------------------------------
extern "C" void kernel_launch(void* const* d_in, const int* in_sizes, int n_in,
                              void* d_out, int out_size) {
    const float* x     = (const float*)d_in[0];
    const float* fc1_w = (const float*)d_in[1];
    const float* fc1_b = (const float*)d_in[2];
    const float* fc2_w = (const float*)d_in[3];
    const float* fc2_b = (const float*)d_in[4];
    const float* fc3_w = (const float*)d_in[5];
    const float* fc3_b = (const float*)d_in[6];
    const float* W_ih  = (const float*)d_in[7];
    // d_in[8] = W_hh   (unused: h_prev == 0)
    const float* b_ih  = (const float*)d_in[9];
    const float* b_hh  = (const float*)d_in[10];
    // d_in[11], d_in[12] = attn_w, attn_b (unused: softmax over len-1 == 1)
    const float* fc_w  = (const float*)d_in[13];
    const float* fc_b  = (const float*)d_in[14];
    float* out = (float*)d_out;

    const int smem2 = 3 * 128 * P2 * 4;  // 202,752 B
    cudaFuncSetAttribute(tail_kernel, cudaFuncAttributeMaxDynamicSharedMemorySize, smem2);

    pack_wb_kernel<<<1024, 256>>>(fc1_w, W_ih);

    dim3 grid1(NROWS / 128, 4);
    gemm1_kernel<<<grid1, 256>>>(x);

    tail_kernel<<<NROWS / 128, 256, smem2>>>(fc1_b, fc2_w, fc2_b, fc3_w, fc3_b,
                                             W_ih, b_ih, b_hh, fc_w, fc_b, out);
}

// round 3
// speedup vs baseline: 1.6135x; 1.6135x over previous
#include <cuda_runtime.h>
#include <cstdint>

// ---------------------------------------------------------------------------
// Fully-fused DNN+LSTM(+degenerate attention), algebraically reduced:
//   Y[B,512] = x @ Wb.T   (Wb = [fc1_w ; W_ih(i,g,o)[:, :512]])  -- in registers
//   tail (per 64-row CTA, all in SMEM/regs):
//     d1=relu(Y0+b); d2=relu(d1@fc2.T+b); d3=d2@fc3.T+b
//     i/g/o = Ygate + d3@Wih[:,512:].T + b ; c=sig(i)tanh(g); h=sig(o)tanh(c)
//     out = h @ fc_w.T + fc_b
//   f-gate, W_hh, attention are dead code. All GEMMs tf32 mma.sync (fp32 acc).
// ---------------------------------------------------------------------------

#define NROWS 131072
#define PT 132     // tail smem pitch (words): 132%32==4 -> conflict-free frags
#define YP 392     // gate staging pitch (floats)

// Big-GEMM weights packed in mma-fragment layout, tf32.
// word idx = tile*16384 + ((k8*64 + n8)*32 + lane)*2 + c
//   element: n = n8*8 + (lane>>2), k = tile*32 + k8*8 + (lane&3) + 4c
__device__ uint32_t g_WbF[512 * 512];

__device__ __forceinline__ uint32_t tf32cvt(float f) {
    uint32_t r;
    asm("cvt.rna.tf32.f32 %0, %1;" : "=r"(r) : "f"(f));
    return r;
}

__device__ __forceinline__ void mma8(float* c, const uint32_t* a, uint32_t b0, uint32_t b1) {
    asm volatile(
        "mma.sync.aligned.m16n8k8.row.col.f32.tf32.tf32.f32 "
        "{%0,%1,%2,%3},{%4,%5,%6,%7},{%8,%9},{%0,%1,%2,%3};"
        : "+f"(c[0]), "+f"(c[1]), "+f"(c[2]), "+f"(c[3])
        : "r"(a[0]), "r"(a[1]), "r"(a[2]), "r"(a[3]), "r"(b0), "r"(b1));
}

__device__ __forceinline__ float sigm(float x) { return 1.0f / (1.0f + expf(-x)); }

__device__ __forceinline__ uint32_t smem_u32(const void* p) {
    return (uint32_t)__cvta_generic_to_shared(p);
}

// ---------------------------------------------------------------------------
// Pack Wb into fragment layout (tf32). Skips dead f-gate rows of W_ih.
// ---------------------------------------------------------------------------
__global__ void pack_kernel(const float* __restrict__ fc1_w,
                            const float* __restrict__ W_ih) {
    int w = blockIdx.x * 256 + threadIdx.x;   // 0..262143
    int tile = w >> 14;
    int k8r  = (w >> 12) & 3;
    int n8   = (w >> 6) & 63;
    int lane = (w >> 1) & 31;
    int c    = w & 1;
    int n = n8 * 8 + (lane >> 2);
    int k = tile * 32 + k8r * 8 + (lane & 3) + 4 * c;
    float v;
    if (n < 128) v = fc1_w[n * 512 + k];
    else { int sr = (n < 256) ? n - 128 : n; v = W_ih[(size_t)sr * 640 + k]; }
    g_WbF[w] = tf32cvt(v);
}

// ---------------------------------------------------------------------------
// tail GEMM: A[64][K] (pitch PT tf32), W[N][K] (pitch PT tf32) -> acc
// 8 warps: twm = warp>>2 (32 rows), twn = warp&3 (NT*8 cols)
// ---------------------------------------------------------------------------
template <int KD, int NT>
__device__ __forceinline__ void tgemm(const uint32_t* __restrict__ sAa,
                                      const uint32_t* __restrict__ sW,
                                      float tac[2][NT][4],
                                      int twm, int twn, int g, int t4) {
#pragma unroll
    for (int kk = 0; kk < KD; kk += 8) {
        uint32_t a[2][4];
#pragma unroll
        for (int mi = 0; mi < 2; mi++) {
            int r = twm * 32 + mi * 16 + g;
            a[mi][0] = sAa[r * PT + kk + t4];
            a[mi][1] = sAa[(r + 8) * PT + kk + t4];
            a[mi][2] = sAa[r * PT + kk + t4 + 4];
            a[mi][3] = sAa[(r + 8) * PT + kk + t4 + 4];
        }
#pragma unroll
        for (int ni = 0; ni < NT; ni++) {
            int n = (twn * NT + ni) * 8 + g;
            uint32_t b0 = sW[n * PT + kk + t4];
            uint32_t b1 = sW[n * PT + kk + t4 + 4];
            mma8(tac[0][ni], a[0], b0, b1);
            mma8(tac[1][ni], a[1], b0, b1);
        }
    }
}

// ---------------------------------------------------------------------------
// Fused kernel: BM=64 rows per CTA, 256 threads.
// ---------------------------------------------------------------------------
__global__ __launch_bounds__(256, 1) void fused_kernel(
    const float* __restrict__ x,
    const float* __restrict__ fc1_b, const float* __restrict__ fc2_w,
    const float* __restrict__ fc2_b, const float* __restrict__ fc3_w,
    const float* __restrict__ fc3_b, const float* __restrict__ W_ih,
    const float* __restrict__ b_ih,  const float* __restrict__ b_hh,
    const float* __restrict__ fc_w,  const float* __restrict__ fc_b,
    float* __restrict__ out) {
    extern __shared__ char smem[];
    // --- mainloop views ---
    uint32_t* sA  = (uint32_t*)smem;                 // [2][64][36]  (18432 B)
    uint32_t* sBm = (uint32_t*)(smem + 18432);       // [2][16384]   (131072 B)
    // --- tail views (aliased; valid after final mainloop sync) ---
    float*    sYg = (float*)smem;                    // [64][YP]     (100352 B)
    uint32_t* B0  = (uint32_t*)(smem + 100352);      // [64][PT]     (33792 B)
    uint32_t* B1  = (uint32_t*)(smem + 134144);      // [128][PT]    (67584 B)

    const int tid  = threadIdx.x;
    const int lane = tid & 31;
    const int warp = tid >> 5;
    const int g    = lane >> 2;
    const int t4   = lane & 3;
    const int wn   = warp;          // mainloop: warp covers cols wn*64..wn*64+63

    const size_t rowbase = (size_t)blockIdx.x * 64;
    const float* xg = x + rowbase * 512;

    // A-tile load assignment: thread loads rows ar0 and ar0+32, cols ac0..ac0+3
    const int ar0 = tid >> 3;
    const int ac0 = (tid & 7) << 2;

    float acc[4][8][4];
#pragma unroll
    for (int mi = 0; mi < 4; mi++)
#pragma unroll
        for (int ni = 0; ni < 8; ni++)
#pragma unroll
            for (int e = 0; e < 4; e++) acc[mi][ni][e] = 0.0f;

    const uint32_t sBm_base = smem_u32(sBm);
    float4 av0, av1;

#define LDA(K0)                                                                 \
    do {                                                                        \
        av0 = *(const float4*)(xg + (size_t)ar0 * 512 + (K0) * 32 + ac0);       \
        av1 = *(const float4*)(xg + (size_t)(ar0 + 32) * 512 + (K0) * 32 + ac0);\
    } while (0)

#define STA(S)                                                                  \
    do {                                                                        \
        uint32_t* d0 = sA + (S) * 2304 + ar0 * 36 + ac0;                        \
        d0[0] = tf32cvt(av0.x); d0[1] = tf32cvt(av0.y);                         \
        d0[2] = tf32cvt(av0.z); d0[3] = tf32cvt(av0.w);                         \
        uint32_t* d1 = sA + (S) * 2304 + (ar0 + 32) * 36 + ac0;                 \
        d1[0] = tf32cvt(av1.x); d1[1] = tf32cvt(av1.y);                         \
        d1[2] = tf32cvt(av1.z); d1[3] = tf32cvt(av1.w);                         \
    } while (0)

#define CPB(K0, S)                                                              \
    do {                                                                        \
        const char* src = (const char*)g_WbF + (size_t)(K0) * 65536 + tid * 16; \
        uint32_t dst = sBm_base + (S) * 65536 + tid * 16;                       \
        _Pragma("unroll")                                                       \
        for (int i_ = 0; i_ < 16; i_++)                                         \
            asm volatile("cp.async.cg.shared.global [%0], [%1], 16;"            \
                         :: "r"(dst + i_ * 4096), "l"(src + i_ * 4096));        \
    } while (0)

    // ---- prologue ----
    LDA(0);
    CPB(0, 0);
    asm volatile("cp.async.commit_group;" ::: "memory");
    STA(0);
    asm volatile("cp.async.wait_group 0;" ::: "memory");
    __syncthreads();

    // ---- mainloop: 16 double-buffered k-tiles ----
#pragma unroll 1
    for (int k0 = 0; k0 < 16; k0++) {
        const int cur = k0 & 1, nxt = cur ^ 1;
        if (k0 < 15) {
            LDA(k0 + 1);
            CPB(k0 + 1, nxt);
            asm volatile("cp.async.commit_group;" ::: "memory");
        }
        const uint32_t* A  = sA + cur * 2304;
        const uint32_t* Bb = sBm + cur * 16384;
#pragma unroll
        for (int k8 = 0; k8 < 4; k8++) {
            uint32_t a[4][4];
#pragma unroll
            for (int mi = 0; mi < 4; mi++) {
                const uint32_t* Ar = A + (mi * 16 + g) * 36 + k8 * 8 + t4;
                a[mi][0] = Ar[0];
                a[mi][1] = Ar[8 * 36];
                a[mi][2] = Ar[4];
                a[mi][3] = Ar[8 * 36 + 4];
            }
#pragma unroll
            for (int ni = 0; ni < 8; ni++) {
                uint2 bb = *(const uint2*)(Bb + ((k8 * 64 + wn * 8 + ni) * 32 + lane) * 2);
#pragma unroll
                for (int mi = 0; mi < 4; mi++) mma8(acc[mi][ni], a[mi], bb.x, bb.y);
            }
        }
        if (k0 < 15) {
            STA(nxt);
            asm volatile("cp.async.wait_group 0;" ::: "memory");
        }
        __syncthreads();
    }

    // =======================================================================
    // Tail (SMEM reuse is safe: final loop iteration ended with __syncthreads)
    // =======================================================================

    // ---- dump acc: d1 -> B0 (warps 0,1), gate staging Y+b -> sYg (warps 2..7)
    if (warp < 2) {
#pragma unroll
        for (int mi = 0; mi < 4; mi++)
#pragma unroll
            for (int ni = 0; ni < 8; ni++) {
                int r = mi * 16 + g;
                int cg = wn * 64 + ni * 8 + t4 * 2;
                B0[r * PT + cg]           = tf32cvt(fmaxf(acc[mi][ni][0] + fc1_b[cg], 0.f));
                B0[r * PT + cg + 1]       = tf32cvt(fmaxf(acc[mi][ni][1] + fc1_b[cg + 1], 0.f));
                B0[(r + 8) * PT + cg]     = tf32cvt(fmaxf(acc[mi][ni][2] + fc1_b[cg], 0.f));
                B0[(r + 8) * PT + cg + 1] = tf32cvt(fmaxf(acc[mi][ni][3] + fc1_b[cg + 1], 0.f));
            }
    } else {
#pragma unroll
        for (int mi = 0; mi < 4; mi++)
#pragma unroll
            for (int ni = 0; ni < 8; ni++) {
                int r = mi * 16 + g;
                int cglob = wn * 64 + ni * 8 + t4 * 2;     // 128..511
                int bi = (cglob < 256) ? cglob - 128 : cglob;
                int jg = cglob - 128;
                float bb0 = b_ih[bi] + b_hh[bi];
                float bb1 = b_ih[bi + 1] + b_hh[bi + 1];
                sYg[r * YP + jg]           = acc[mi][ni][0] + bb0;
                sYg[r * YP + jg + 1]       = acc[mi][ni][1] + bb1;
                sYg[(r + 8) * YP + jg]     = acc[mi][ni][2] + bb0;
                sYg[(r + 8) * YP + jg + 1] = acc[mi][ni][3] + bb1;
            }
    }
    // load fc2_w (64x128) -> B1
    for (int i = tid; i < 64 * 32; i += 256) {
        int r = i >> 5, c4 = (i & 31) << 2;
        float4 v = *(const float4*)(fc2_w + r * 128 + c4);
        uint32_t* d = B1 + r * PT + c4;
        d[0] = tf32cvt(v.x); d[1] = tf32cvt(v.y); d[2] = tf32cvt(v.z); d[3] = tf32cvt(v.w);
    }
    __syncthreads();

    const int twm = warp >> 2;   // 0..1
    const int twn = warp & 3;    // 0..3

    // ---- G1: d2 = relu(d1 @ fc2_w.T + fc2_b)  (K=128, N=64) ----
    {
        float tac[2][2][4];
#pragma unroll
        for (int mi = 0; mi < 2; mi++)
#pragma unroll
            for (int ni = 0; ni < 2; ni++)
#pragma unroll
                for (int e = 0; e < 4; e++) tac[mi][ni][e] = 0.f;
        tgemm<128, 2>(B0, B1, tac, twm, twn, g, t4);
        __syncthreads();
#pragma unroll
        for (int mi = 0; mi < 2; mi++)
#pragma unroll
            for (int ni = 0; ni < 2; ni++) {
                int r = twm * 32 + mi * 16 + g;
                int c = (twn * 2 + ni) * 8 + t4 * 2;
                B0[r * PT + c]           = tf32cvt(fmaxf(tac[mi][ni][0] + fc2_b[c], 0.f));
                B0[r * PT + c + 1]       = tf32cvt(fmaxf(tac[mi][ni][1] + fc2_b[c + 1], 0.f));
                B0[(r + 8) * PT + c]     = tf32cvt(fmaxf(tac[mi][ni][2] + fc2_b[c], 0.f));
                B0[(r + 8) * PT + c + 1] = tf32cvt(fmaxf(tac[mi][ni][3] + fc2_b[c + 1], 0.f));
            }
    }
    // load fc3_w (128x64) -> B1
    for (int i = tid; i < 128 * 16; i += 256) {
        int r = i >> 4, c4 = (i & 15) << 2;
        float4 v = *(const float4*)(fc3_w + r * 64 + c4);
        uint32_t* d = B1 + r * PT + c4;
        d[0] = tf32cvt(v.x); d[1] = tf32cvt(v.y); d[2] = tf32cvt(v.z); d[3] = tf32cvt(v.w);
    }
    __syncthreads();

    // ---- G2: d3 = d2 @ fc3_w.T + fc3_b  (K=64, N=128) ----
    {
        float tac[2][4][4];
#pragma unroll
        for (int mi = 0; mi < 2; mi++)
#pragma unroll
            for (int ni = 0; ni < 4; ni++)
#pragma unroll
                for (int e = 0; e < 4; e++) tac[mi][ni][e] = 0.f;
        tgemm<64, 4>(B0, B1, tac, twm, twn, g, t4);
        __syncthreads();
#pragma unroll
        for (int mi = 0; mi < 2; mi++)
#pragma unroll
            for (int ni = 0; ni < 4; ni++) {
                int r = twm * 32 + mi * 16 + g;
                int c = (twn * 4 + ni) * 8 + t4 * 2;
                B0[r * PT + c]           = tf32cvt(tac[mi][ni][0] + fc3_b[c]);
                B0[r * PT + c + 1]       = tf32cvt(tac[mi][ni][1] + fc3_b[c + 1]);
                B0[(r + 8) * PT + c]     = tf32cvt(tac[mi][ni][2] + fc3_b[c]);
                B0[(r + 8) * PT + c + 1] = tf32cvt(tac[mi][ni][3] + fc3_b[c + 1]);
            }
    }
    // load W_ih gate i rows (0..127), cols 512.. -> B1
    for (int i = tid; i < 128 * 32; i += 256) {
        int r = i >> 5, c4 = (i & 31) << 2;
        float4 v = *(const float4*)(W_ih + (size_t)r * 640 + 512 + c4);
        uint32_t* d = B1 + r * PT + c4;
        d[0] = tf32cvt(v.x); d[1] = tf32cvt(v.y); d[2] = tf32cvt(v.z); d[3] = tf32cvt(v.w);
    }
    __syncthreads();

    // ---- gates i, g, o : carry i -> c in registers, h -> B0 ----
    float carry[2][4][4];
#pragma unroll 1
    for (int blk = 0; blk < 3; blk++) {
        float tac[2][4][4];
#pragma unroll
        for (int mi = 0; mi < 2; mi++)
#pragma unroll
            for (int ni = 0; ni < 4; ni++)
#pragma unroll
                for (int e = 0; e < 4; e++) tac[mi][ni][e] = 0.f;
        tgemm<128, 4>(B0, B1, tac, twm, twn, g, t4);
        __syncthreads();
#pragma unroll
        for (int mi = 0; mi < 2; mi++)
#pragma unroll
            for (int ni = 0; ni < 4; ni++)
#pragma unroll
                for (int e = 0; e < 4; e++) {
                    int r = twm * 32 + mi * 16 + g + ((e >> 1) ? 8 : 0);
                    int j = (twn * 4 + ni) * 8 + t4 * 2 + (e & 1);
                    float v = tac[mi][ni][e] + sYg[r * YP + blk * 128 + j];
                    if (blk == 0)      carry[mi][ni][e] = v;                       // i
                    else if (blk == 1) carry[mi][ni][e] = sigm(carry[mi][ni][e]) * tanhf(v); // c
                    else               B0[r * PT + j] = tf32cvt(sigm(v) * tanhf(carry[mi][ni][e])); // h
                }
        // next weights
        if (blk < 2) {
            int gbase = (blk == 0) ? 256 : 384;
            for (int i = tid; i < 128 * 32; i += 256) {
                int r = i >> 5, c4 = (i & 31) << 2;
                float4 v = *(const float4*)(W_ih + (size_t)(gbase + r) * 640 + 512 + c4);
                uint32_t* d = B1 + r * PT + c4;
                d[0] = tf32cvt(v.x); d[1] = tf32cvt(v.y); d[2] = tf32cvt(v.z); d[3] = tf32cvt(v.w);
            }
        } else {
            for (int i = tid; i < 128 * 32; i += 256) {
                int r = i >> 5, c4 = (i & 31) << 2;
                float4 v = *(const float4*)(fc_w + r * 128 + c4);
                uint32_t* d = B1 + r * PT + c4;
                d[0] = tf32cvt(v.x); d[1] = tf32cvt(v.y); d[2] = tf32cvt(v.z); d[3] = tf32cvt(v.w);
            }
        }
        __syncthreads();
    }

    // ---- G4: out = h @ fc_w.T + fc_b  (K=128, N=128) ----
    {
        float tac[2][4][4];
#pragma unroll
        for (int mi = 0; mi < 2; mi++)
#pragma unroll
            for (int ni = 0; ni < 4; ni++)
#pragma unroll
                for (int e = 0; e < 4; e++) tac[mi][ni][e] = 0.f;
        tgemm<128, 4>(B0, B1, tac, twm, twn, g, t4);
#pragma unroll
        for (int mi = 0; mi < 2; mi++)
#pragma unroll
            for (int ni = 0; ni < 4; ni++) {
                int r = twm * 32 + mi * 16 + g;
                int c = (twn * 4 + ni) * 8 + t4 * 2;
                *(float2*)(out + (rowbase + r) * 128 + c) =
                    make_float2(tac[mi][ni][0] + fc_b[c], tac[mi][ni][1] + fc_b[c + 1]);
                *(float2*)(out + (rowbase + r + 8) * 128 + c) =
                    make_float2(tac[mi][ni][2] + fc_b[c], tac[mi][ni][3] + fc_b[c + 1]);
            }
    }
#undef LDA
#undef STA
#undef CPB
}

// ---------------------------------------------------------------------------
extern "C" void kernel_launch(void* const* d_in, const int* in_sizes, int n_in,
                              void* d_out, int out_size) {
    const float* x     = (const float*)d_in[0];
    const float* fc1_w = (const float*)d_in[1];
    const float* fc1_b = (const float*)d_in[2];
    const float* fc2_w = (const float*)d_in[3];
    const float* fc2_b = (const float*)d_in[4];
    const float* fc3_w = (const float*)d_in[5];
    const float* fc3_b = (const float*)d_in[6];
    const float* W_ih  = (const float*)d_in[7];
    // d_in[8] = W_hh (dead: h_prev == 0)
    const float* b_ih  = (const float*)d_in[9];
    const float* b_hh  = (const float*)d_in[10];
    // d_in[11..12] = attn_w, attn_b (dead: softmax over length-1 seq == 1)
    const float* fc_w  = (const float*)d_in[13];
    const float* fc_b  = (const float*)d_in[14];
    float* out = (float*)d_out;

    const int smem = 201728;  // max(mainloop 149504, tail 201728)
    static int configured = 0;
    cudaFuncSetAttribute(fused_kernel, cudaFuncAttributeMaxDynamicSharedMemorySize, smem);
    (void)configured;

    pack_kernel<<<1024, 256>>>(fc1_w, W_ih);
    fused_kernel<<<NROWS / 64, 256, smem>>>(x, fc1_b, fc2_w, fc2_b, fc3_w, fc3_b,
                                            W_ih, b_ih, b_hh, fc_w, fc_b, out);
}

// round 5
// speedup vs baseline: 1.6279x; 1.0089x over previous
#include <cuda_runtime.h>
#include <cstdint>

// ===========================================================================
// DNN+LSTM fused (tcgen05 unavailable: harness PTX target is sm_103 plain).
//   Y[B,512] = x @ Wb.T   (Wb = [fc1_w ; W_ih(i,g,o)[:, :512]]) -- in regs
//   d1=relu(Y0+b); d2=relu(d1@fc2.T+b); d3=d2@fc3.T+b
//   i/g/o = Ygate + d3@Wih[:,512:].T + b ; c=sig(i)tanh(g); h=sig(o)tanh(c)
//   out = h @ fc_w.T + fc_b
// f-gate, W_hh, attention are dead code. All GEMMs tf32 mma.sync (fp32 acc).
// 512 threads/CTA (16 warps) for latency hiding; paired LDS.64/LDS.128 frags.
// ===========================================================================

#define NROWS 131072
#define PT 132

// B pre-packed tf32 in ni-PAIRED mma fragment layout:
// word w: tile=w>>14; rem=w&16383; q=rem&3; lane=(rem>>2)&31; p=(rem>>7)&31; k8=rem>>12
//   n8 = 2p + (q>>1); n = n8*8 + (lane>>2); k = tile*32 + k8*8 + (lane&3) + 4*(q&1)
__device__ __align__(1024) uint32_t g_WbF[512 * 512];

__device__ __forceinline__ uint32_t tf32cvt(float f) {
    uint32_t r; asm("cvt.rna.tf32.f32 %0, %1;" : "=r"(r) : "f"(f)); return r;
}
__device__ __forceinline__ void mma8(float* c, const uint32_t* a, uint32_t b0, uint32_t b1) {
    asm volatile(
        "mma.sync.aligned.m16n8k8.row.col.f32.tf32.tf32.f32 "
        "{%0,%1,%2,%3},{%4,%5,%6,%7},{%8,%9},{%0,%1,%2,%3};"
        : "+f"(c[0]), "+f"(c[1]), "+f"(c[2]), "+f"(c[3])
        : "r"(a[0]), "r"(a[1]), "r"(a[2]), "r"(a[3]), "r"(b0), "r"(b1));
}
__device__ __forceinline__ float sigm(float x) { return 1.0f / (1.0f + expf(-x)); }
__device__ __forceinline__ uint32_t smem_u32(const void* p) {
    return (uint32_t)__cvta_generic_to_shared(p);
}

// ---------------------------------------------------------------------------
__global__ void pack_kernel(const float* __restrict__ fc1_w,
                            const float* __restrict__ W_ih) {
    int w = blockIdx.x * 256 + threadIdx.x;
    int tile = w >> 14;
    int rem  = w & 16383;
    int q    = rem & 3;
    int lane = (rem >> 2) & 31;
    int p    = (rem >> 7) & 31;
    int k8   = rem >> 12;
    int n8 = 2 * p + (q >> 1);
    int n  = n8 * 8 + (lane >> 2);
    int k  = tile * 32 + k8 * 8 + (lane & 3) + 4 * (q & 1);
    float v;
    if (n < 128) v = fc1_w[n * 512 + k];
    else { int sr = (n < 256) ? n - 128 : n; v = W_ih[(size_t)sr * 640 + k]; }
    g_WbF[w] = tf32cvt(v);
}

// ---------------------------------------------------------------------------
// tail GEMM, 16 warps: twm=warp>>3 (2 row groups of 32), twn=warp&7 (8 col grp)
// ---------------------------------------------------------------------------
template <int KD, int NT>
__device__ __forceinline__ void tgemm16(const uint32_t* __restrict__ sAa,
                                        const uint32_t* __restrict__ sW,
                                        float tac[2][NT][4],
                                        int twm, int twn, int g, int t4) {
#pragma unroll
    for (int kk = 0; kk < KD; kk += 8) {
        uint32_t a[2][4];
#pragma unroll
        for (int mi = 0; mi < 2; mi++) {
            int r = twm * 32 + mi * 16 + g;
            a[mi][0] = sAa[r * PT + kk + t4];
            a[mi][1] = sAa[(r + 8) * PT + kk + t4];
            a[mi][2] = sAa[r * PT + kk + t4 + 4];
            a[mi][3] = sAa[(r + 8) * PT + kk + t4 + 4];
        }
#pragma unroll
        for (int ni = 0; ni < NT; ni++) {
            int n = (twn * NT + ni) * 8 + g;
            uint32_t b0 = sW[n * PT + kk + t4];
            uint32_t b1 = sW[n * PT + kk + t4 + 4];
            mma8(tac[0][ni], a[0], b0, b1);
            mma8(tac[1][ni], a[1], b0, b1);
        }
    }
}

// ---------------------------------------------------------------------------
// Fused kernel: BM=64 rows/CTA, 512 threads (16 warps).
// mainloop smem: sA [2][64][40]w @0 (20480B), sB [2][16384]w @20480 (131072B)
// tail smem:     B0 @0 (33792B), B1 @33792 (67584B), B2 @101376 (33792B)
// ---------------------------------------------------------------------------
__global__ __launch_bounds__(512, 1) void fused_kernel(
    const float* __restrict__ x,
    const float* __restrict__ fc1_b, const float* __restrict__ fc2_w,
    const float* __restrict__ fc2_b, const float* __restrict__ fc3_w,
    const float* __restrict__ fc3_b, const float* __restrict__ W_ih,
    const float* __restrict__ b_ih,  const float* __restrict__ b_hh,
    const float* __restrict__ fc_w,  const float* __restrict__ fc_b,
    float* __restrict__ out) {
    extern __shared__ char smem[];
    uint32_t* sAp = (uint32_t*)smem;                  // [2][2560] words
    uint32_t* sBp = (uint32_t*)(smem + 20480);        // [2][16384] words
    const uint32_t sB_base = smem_u32(sBp);

    const int tid  = threadIdx.x;
    const int lane = tid & 31;
    const int warp = tid >> 5;
    const int g    = lane >> 2;
    const int t4   = lane & 3;
    const int wr   = warp >> 3;     // 0..1  (32-row group)
    const int wc   = warp & 7;      // 0..7  (64-col group)

    const size_t rowbase = (size_t)blockIdx.x * 64;
    const float* xg = x + rowbase * 512;

    const int r_ = tid >> 3;              // 0..63
    const int c_ = (tid & 7) << 2;        // 0,4,...,28

    float acc[2][8][4];
#pragma unroll
    for (int mi = 0; mi < 2; mi++)
#pragma unroll
        for (int ni = 0; ni < 8; ni++)
#pragma unroll
            for (int e = 0; e < 4; e++) acc[mi][ni][e] = 0.0f;

    float4 av;

#define LDA(K0) do { av = *(const float4*)(xg + (size_t)r_ * 512 + (K0) * 32 + c_); } while (0)

// store with k-permutation: pos(k) = (k>>3)*8 + ((k&3)<<1) + ((k>>2)&1)
#define STA(S) do { \
    float vv_[4] = {av.x, av.y, av.z, av.w}; \
    _Pragma("unroll") \
    for (int j_ = 0; j_ < 4; j_++) { \
        int k_ = c_ + j_; \
        int pos_ = ((k_ >> 3) << 3) + ((k_ & 3) << 1) + ((k_ >> 2) & 1); \
        sAp[(S) * 2560 + r_ * 40 + pos_] = tf32cvt(vv_[j_]); \
    } \
} while (0)

#define CPB(K0, S) do { \
    const char* src_ = (const char*)g_WbF + (size_t)(K0) * 65536 + tid * 16; \
    uint32_t dst_ = sB_base + (S) * 65536 + tid * 16; \
    _Pragma("unroll") \
    for (int i_ = 0; i_ < 8; i_++) \
        asm volatile("cp.async.cg.shared.global [%0], [%1], 16;" \
                     :: "r"(dst_ + i_ * 8192), "l"(src_ + i_ * 8192)); \
    asm volatile("cp.async.commit_group;" ::: "memory"); \
} while (0)

    // ---- prologue ----
    LDA(0);
    CPB(0, 0);
    STA(0);
    asm volatile("cp.async.wait_group 0;" ::: "memory");
    __syncthreads();

    // ---- mainloop: 16 double-buffered k-tiles ----
#pragma unroll 1
    for (int k0 = 0; k0 < 16; k0++) {
        const int cur = k0 & 1, nxt = cur ^ 1;
        if (k0 < 15) {
            LDA(k0 + 1);
            CPB(k0 + 1, nxt);
        }
#pragma unroll
        for (int k8 = 0; k8 < 4; k8++) {
            uint2 pa[2][2];
#pragma unroll
            for (int mi = 0; mi < 2; mi++) {
                const uint32_t* base = sAp + cur * 2560 +
                    (wr * 32 + mi * 16 + g) * 40 + k8 * 8 + 2 * t4;
                pa[mi][0] = *(const uint2*)base;
                pa[mi][1] = *(const uint2*)(base + 8 * 40);
            }
#pragma unroll
            for (int pi = 0; pi < 4; pi++) {
                uint4 bq = *(const uint4*)(sBp + cur * 16384 +
                    ((k8 * 32 + wc * 4 + pi) * 32 + lane) * 4);
#pragma unroll
                for (int mi = 0; mi < 2; mi++) {
                    uint32_t a[4] = {pa[mi][0].x, pa[mi][1].x, pa[mi][0].y, pa[mi][1].y};
                    mma8(acc[mi][2 * pi],     a, bq.x, bq.y);
                    mma8(acc[mi][2 * pi + 1], a, bq.z, bq.w);
                }
            }
        }
        if (k0 < 15) {
            STA(nxt);
            asm volatile("cp.async.wait_group 0;" ::: "memory");
        }
        __syncthreads();
    }

    // ======================= tail =======================
    uint32_t* B0 = (uint32_t*)smem;                 // 64 x PT
    uint32_t* B1 = (uint32_t*)(smem + 33792);       // 128 x PT
    float*    B2f = (float*)(smem + 101376);        // 64 x PT (f32 staging)

    const int twm = warp >> 3;
    const int twn = warp & 7;

    // S0: d1 -> B0 (wc 0,1); stage gate-i Y+bias -> B2 (wc 2,3); fc2_w -> B1
    if (wc < 2) {
#pragma unroll
        for (int mi = 0; mi < 2; mi++)
#pragma unroll
            for (int ni = 0; ni < 8; ni++) {
                int r = wr * 32 + mi * 16 + g;
                int cg = wc * 64 + ni * 8 + t4 * 2;
                B0[r * PT + cg]           = tf32cvt(fmaxf(acc[mi][ni][0] + fc1_b[cg], 0.f));
                B0[r * PT + cg + 1]       = tf32cvt(fmaxf(acc[mi][ni][1] + fc1_b[cg + 1], 0.f));
                B0[(r + 8) * PT + cg]     = tf32cvt(fmaxf(acc[mi][ni][2] + fc1_b[cg], 0.f));
                B0[(r + 8) * PT + cg + 1] = tf32cvt(fmaxf(acc[mi][ni][3] + fc1_b[cg + 1], 0.f));
            }
    } else if (wc < 4) {
#pragma unroll
        for (int mi = 0; mi < 2; mi++)
#pragma unroll
            for (int ni = 0; ni < 8; ni++)
#pragma unroll
                for (int e = 0; e < 4; e++) {
                    int r = wr * 32 + mi * 16 + g + ((e >> 1) ? 8 : 0);
                    int cg = wc * 64 + ni * 8 + t4 * 2 + (e & 1);
                    int j = cg - 128;                 // gate-i col; bias idx = j
                    B2f[r * PT + j] = acc[mi][ni][e] + b_ih[j] + b_hh[j];
                }
    }
    for (int i = tid; i < 64 * 32; i += 512) {
        int r = i >> 5, c4 = (i & 31) << 2;
        float4 v = *(const float4*)(fc2_w + r * 128 + c4);
        uint32_t* d = B1 + r * PT + c4;
        d[0] = tf32cvt(v.x); d[1] = tf32cvt(v.y); d[2] = tf32cvt(v.z); d[3] = tf32cvt(v.w);
    }
    __syncthreads();

    // S1: G1 d2 = relu(d1 @ fc2_w.T + b)  K=128, N=64
    float tac1[2][1][4];
#pragma unroll
    for (int mi = 0; mi < 2; mi++)
#pragma unroll
        for (int e = 0; e < 4; e++) tac1[mi][0][e] = 0.f;
    tgemm16<128, 1>(B0, B1, tac1, twm, twn, g, t4);
    __syncthreads();

    // S2: d2 -> B0 cols 0..63 ; fc3_w -> B1
    {
        int c = twn * 8 + t4 * 2;
#pragma unroll
        for (int mi = 0; mi < 2; mi++) {
            int r = twm * 32 + mi * 16 + g;
            B0[r * PT + c]           = tf32cvt(fmaxf(tac1[mi][0][0] + fc2_b[c], 0.f));
            B0[r * PT + c + 1]       = tf32cvt(fmaxf(tac1[mi][0][1] + fc2_b[c + 1], 0.f));
            B0[(r + 8) * PT + c]     = tf32cvt(fmaxf(tac1[mi][0][2] + fc2_b[c], 0.f));
            B0[(r + 8) * PT + c + 1] = tf32cvt(fmaxf(tac1[mi][0][3] + fc2_b[c + 1], 0.f));
        }
    }
    for (int i = tid; i < 128 * 16; i += 512) {
        int r = i >> 4, c4 = (i & 15) << 2;
        float4 v = *(const float4*)(fc3_w + r * 64 + c4);
        uint32_t* d = B1 + r * PT + c4;
        d[0] = tf32cvt(v.x); d[1] = tf32cvt(v.y); d[2] = tf32cvt(v.z); d[3] = tf32cvt(v.w);
    }
    __syncthreads();

    // S3: G2 d3 = d2 @ fc3_w.T + b  K=64, N=128
    float tac[2][2][4];
#pragma unroll
    for (int mi = 0; mi < 2; mi++)
#pragma unroll
        for (int ni = 0; ni < 2; ni++)
#pragma unroll
            for (int e = 0; e < 4; e++) tac[mi][ni][e] = 0.f;
    tgemm16<64, 2>(B0, B1, tac, twm, twn, g, t4);
    __syncthreads();

    // S4: d3 -> B0 ; Wih_i -> B1
#pragma unroll
    for (int mi = 0; mi < 2; mi++)
#pragma unroll
        for (int ni = 0; ni < 2; ni++) {
            int r = twm * 32 + mi * 16 + g;
            int c = (twn * 2 + ni) * 8 + t4 * 2;
            B0[r * PT + c]           = tf32cvt(tac[mi][ni][0] + fc3_b[c]);
            B0[r * PT + c + 1]       = tf32cvt(tac[mi][ni][1] + fc3_b[c + 1]);
            B0[(r + 8) * PT + c]     = tf32cvt(tac[mi][ni][2] + fc3_b[c]);
            B0[(r + 8) * PT + c + 1] = tf32cvt(tac[mi][ni][3] + fc3_b[c + 1]);
        }
    for (int i = tid; i < 128 * 32; i += 512) {
        int r = i >> 5, c4 = (i & 31) << 2;
        float4 v = *(const float4*)(W_ih + (size_t)r * 640 + 512 + c4);
        uint32_t* d = B1 + r * PT + c4;
        d[0] = tf32cvt(v.x); d[1] = tf32cvt(v.y); d[2] = tf32cvt(v.z); d[3] = tf32cvt(v.w);
    }
    __syncthreads();

    // gates i, g, o
    float carry[2][2][4];
#pragma unroll 1
    for (int blk = 0; blk < 3; blk++) {
#pragma unroll
        for (int mi = 0; mi < 2; mi++)
#pragma unroll
            for (int ni = 0; ni < 2; ni++)
#pragma unroll
                for (int e = 0; e < 4; e++) tac[mi][ni][e] = 0.f;
        tgemm16<128, 2>(B0, B1, tac, twm, twn, g, t4);
#pragma unroll
        for (int mi = 0; mi < 2; mi++)
#pragma unroll
            for (int ni = 0; ni < 2; ni++)
#pragma unroll
                for (int e = 0; e < 4; e++) {
                    int r = twm * 32 + mi * 16 + g + ((e >> 1) ? 8 : 0);
                    int j = (twn * 2 + ni) * 8 + t4 * 2 + (e & 1);
                    float v = tac[mi][ni][e] + B2f[r * PT + j];
                    if (blk == 0)      carry[mi][ni][e] = v;
                    else if (blk == 1) carry[mi][ni][e] = sigm(carry[mi][ni][e]) * tanhf(v);
                    else               carry[mi][ni][e] = sigm(v) * tanhf(carry[mi][ni][e]);
                }
        __syncthreads();
        if (blk < 2) {
            // stage next gate's Y+bias (warps owning those Y cols) -> B2
            const int wlo = 4 + 2 * blk;            // wc pair owning next gate
            const int boff = (blk == 0) ? 256 : 384;
            if (wc == wlo || wc == wlo + 1) {
#pragma unroll
                for (int mi = 0; mi < 2; mi++)
#pragma unroll
                    for (int ni = 0; ni < 8; ni++)
#pragma unroll
                        for (int e = 0; e < 4; e++) {
                            int r = wr * 32 + mi * 16 + g + ((e >> 1) ? 8 : 0);
                            int cg = wc * 64 + ni * 8 + t4 * 2 + (e & 1);
                            int j = cg - (blk + 2) * 128;
                            B2f[r * PT + j] = acc[mi][ni][e] + b_ih[boff + j] + b_hh[boff + j];
                        }
            }
            const int wrow = (blk == 0) ? 256 : 384;
            for (int i = tid; i < 128 * 32; i += 512) {
                int r = i >> 5, c4 = (i & 31) << 2;
                float4 v = *(const float4*)(W_ih + (size_t)(wrow + r) * 640 + 512 + c4);
                uint32_t* d = B1 + r * PT + c4;
                d[0] = tf32cvt(v.x); d[1] = tf32cvt(v.y); d[2] = tf32cvt(v.z); d[3] = tf32cvt(v.w);
            }
        } else {
            // h -> B0 ; fc_w -> B1
#pragma unroll
            for (int mi = 0; mi < 2; mi++)
#pragma unroll
                for (int ni = 0; ni < 2; ni++)
#pragma unroll
                    for (int e = 0; e < 4; e++) {
                        int r = twm * 32 + mi * 16 + g + ((e >> 1) ? 8 : 0);
                        int j = (twn * 2 + ni) * 8 + t4 * 2 + (e & 1);
                        B0[r * PT + j] = tf32cvt(carry[mi][ni][e]);
                    }
            for (int i = tid; i < 128 * 32; i += 512) {
                int r = i >> 5, c4 = (i & 31) << 2;
                float4 v = *(const float4*)(fc_w + r * 128 + c4);
                uint32_t* d = B1 + r * PT + c4;
                d[0] = tf32cvt(v.x); d[1] = tf32cvt(v.y); d[2] = tf32cvt(v.z); d[3] = tf32cvt(v.w);
            }
        }
        __syncthreads();
    }

    // G4: out = h @ fc_w.T + fc_b
#pragma unroll
    for (int mi = 0; mi < 2; mi++)
#pragma unroll
        for (int ni = 0; ni < 2; ni++)
#pragma unroll
            for (int e = 0; e < 4; e++) tac[mi][ni][e] = 0.f;
    tgemm16<128, 2>(B0, B1, tac, twm, twn, g, t4);
#pragma unroll
    for (int mi = 0; mi < 2; mi++)
#pragma unroll
        for (int ni = 0; ni < 2; ni++) {
            int r = twm * 32 + mi * 16 + g;
            int c = (twn * 2 + ni) * 8 + t4 * 2;
            *(float2*)(out + (rowbase + r) * 128 + c) =
                make_float2(tac[mi][ni][0] + fc_b[c], tac[mi][ni][1] + fc_b[c + 1]);
            *(float2*)(out + (rowbase + r + 8) * 128 + c) =
                make_float2(tac[mi][ni][2] + fc_b[c], tac[mi][ni][3] + fc_b[c + 1]);
        }
#undef LDA
#undef STA
#undef CPB
}

// ---------------------------------------------------------------------------
extern "C" void kernel_launch(void* const* d_in, const int* in_sizes, int n_in,
                              void* d_out, int out_size) {
    const float* x     = (const float*)d_in[0];
    const float* fc1_w = (const float*)d_in[1];
    const float* fc1_b = (const float*)d_in[2];
    const float* fc2_w = (const float*)d_in[3];
    const float* fc2_b = (const float*)d_in[4];
    const float* fc3_w = (const float*)d_in[5];
    const float* fc3_b = (const float*)d_in[6];
    const float* W_ih  = (const float*)d_in[7];
    // d_in[8] = W_hh (dead: h_prev == 0)
    const float* b_ih  = (const float*)d_in[9];
    const float* b_hh  = (const float*)d_in[10];
    // d_in[11..12] = attn_w, attn_b (dead: softmax over length-1 seq == 1)
    const float* fc_w  = (const float*)d_in[13];
    const float* fc_b  = (const float*)d_in[14];
    float* out = (float*)d_out;

    const int smem = 151552;  // max(mainloop 151552, tail 135168)
    cudaFuncSetAttribute(fused_kernel, cudaFuncAttributeMaxDynamicSharedMemorySize, smem);

    pack_kernel<<<1024, 256>>>(fc1_w, W_ih);
    fused_kernel<<<NROWS / 64, 512, smem>>>(x, fc1_b, fc2_w, fc2_b, fc3_w, fc3_b,
                                            W_ih, b_ih, b_hh, fc_w, fc_b, out);
}

// round 8
// speedup vs baseline: 1.6333x; 1.0033x over previous
#include <cuda_runtime.h>
#include <cuda_fp16.h>
#include <cstdint>

// ===========================================================================
// DNN+LSTM fused, ALL GEMMs on fp16 mma.sync.m16n8k16 (f32 accumulate).
// fp16 mantissa (11 bit) == tf32 mantissa -> same accuracy, 2x throughput.
//   Y[B,512] = x @ Wb.T   (Wb = [fc1_w ; W_ih(i,g,o)[:, :512]]) -- in regs
//   d1=relu(Y0+b); d2=relu(d1@fc2.T+b); d3=d2@fc3.T+b
//   i/g/o = Ygate + d3@Wih[:,512:].T + b ; c=sig(i)tanh(g); h=sig(o)tanh(c)
//   out = h @ fc_w.T + fc_b        (f-gate, W_hh, attention are dead code)
// ===========================================================================

#define NROWS 131072
#define PTF 132    // f32 gate-staging pitch (words)
#define PH 72      // tail half-layout pitch (32-bit words), 72%32==8 -> no conflicts
#define PA 40      // mainloop A pitch (words), 40%32==8 -> no conflicts

// B packed fp16, ni-paired mma-fragment layout, per 64-k tile (8 tiles x 64KB):
// word w: tile=w>>14; rem=w&16383; step=rem>>12; p=(rem>>7)&31; lane=(rem>>2)&31; q=rem&3
//   n = (2p + (q>>1))*8 + (lane>>2);  k = tile*64 + step*16 + 2*(lane&3) + 8*(q&1)
//   word = half2( Wb[n][k], Wb[n][k+1] )
__device__ __align__(1024) uint32_t g_WbF[131072];   // 512 KB

__device__ __forceinline__ uint32_t h2pack(float a, float b) {
    __half2 h = __floats2half2_rn(a, b);
    return *reinterpret_cast<uint32_t*>(&h);
}
__device__ __forceinline__ void mma16(float* c, uint32_t a0, uint32_t a1,
                                      uint32_t a2, uint32_t a3,
                                      uint32_t b0, uint32_t b1) {
    asm volatile(
        "mma.sync.aligned.m16n8k16.row.col.f32.f16.f16.f32 "
        "{%0,%1,%2,%3},{%4,%5,%6,%7},{%8,%9},{%0,%1,%2,%3};"
        : "+f"(c[0]), "+f"(c[1]), "+f"(c[2]), "+f"(c[3])
        : "r"(a0), "r"(a1), "r"(a2), "r"(a3), "r"(b0), "r"(b1));
}
__device__ __forceinline__ float sigm(float x) { return 1.0f / (1.0f + expf(-x)); }
__device__ __forceinline__ uint32_t smem_u32(const void* p) {
    return (uint32_t)__cvta_generic_to_shared(p);
}
// word index (within a permuted row) holding halfs (k, k+1), k even:
__device__ __forceinline__ int kword(int k) {
    int kk = k & 15;
    return (k >> 4) * 8 + ((kk & 7) >> 1) * 2 + ((kk >> 3) & 1);
}

// ---------------------------------------------------------------------------
__global__ void pack_kernel(const float* __restrict__ fc1_w,
                            const float* __restrict__ W_ih) {
    int w = blockIdx.x * 256 + threadIdx.x;    // 0..131071
    int tile = w >> 14;
    int rem  = w & 16383;
    int step = rem >> 12;
    int p    = (rem >> 7) & 31;
    int lane = (rem >> 2) & 31;
    int q    = rem & 3;
    int n = (2 * p + (q >> 1)) * 8 + (lane >> 2);
    int k = tile * 64 + step * 16 + 2 * (lane & 3) + 8 * (q & 1);
    float v0, v1;
    if (n < 128) { v0 = fc1_w[n * 512 + k]; v1 = fc1_w[n * 512 + k + 1]; }
    else {
        int sr = (n < 256) ? n - 128 : n;
        v0 = W_ih[(size_t)sr * 640 + k]; v1 = W_ih[(size_t)sr * 640 + k + 1];
    }
    g_WbF[w] = h2pack(v0, v1);
}

// ---------------------------------------------------------------------------
// tail GEMM (fp16, permuted rows): A[.. ][K] pitch PAa, W[N][K] pitch PW
// 16 warps: twm = warp>>3 (32-row group), twn = warp&7 (NT*8-col group)
// ---------------------------------------------------------------------------
template <int KSTEPS, int NT, int PAa, int PW>
__device__ __forceinline__ void tgemm_h(const uint32_t* __restrict__ sAa,
                                        const uint32_t* __restrict__ sW,
                                        float tac[2][NT][4],
                                        int twm, int twn, int g, int t4) {
#pragma unroll
    for (int s = 0; s < KSTEPS; s++) {
        uint2 alo[2], ahi[2];
#pragma unroll
        for (int mi = 0; mi < 2; mi++) {
            const uint32_t* ap = sAa + (twm * 32 + mi * 16 + g) * PAa + s * 8 + t4 * 2;
            alo[mi] = *(const uint2*)ap;
            ahi[mi] = *(const uint2*)(ap + 8 * PAa);
        }
#pragma unroll
        for (int ni = 0; ni < NT; ni++) {
            int n = (twn * NT + ni) * 8 + g;
            uint2 b = *(const uint2*)(sW + n * PW + s * 8 + t4 * 2);
#pragma unroll
            for (int mi = 0; mi < 2; mi++)
                mma16(tac[mi][ni], alo[mi].x, ahi[mi].x, alo[mi].y, ahi[mi].y, b.x, b.y);
        }
    }
}

// ---------------------------------------------------------------------------
// Fused kernel: BM=64 rows/CTA, 512 threads (16 warps).
// mainloop smem: sA [2][64][40]w @0 (20480B), sB [2][16384]w @20480 (131072B)
// tail smem:     B0h @0 (64x72w, 18432B), B1h @18432 (128x72w, 36864B),
//                B2f @55296 (64x132 f32, 33792B)
// ---------------------------------------------------------------------------
__global__ __launch_bounds__(512, 1) void fused_kernel(
    const float* __restrict__ x,
    const float* __restrict__ fc1_b, const float* __restrict__ fc2_w,
    const float* __restrict__ fc2_b, const float* __restrict__ fc3_w,
    const float* __restrict__ fc3_b, const float* __restrict__ W_ih,
    const float* __restrict__ b_ih,  const float* __restrict__ b_hh,
    const float* __restrict__ fc_w,  const float* __restrict__ fc_b,
    float* __restrict__ out) {
    extern __shared__ char smem[];
    uint32_t* sAp = (uint32_t*)smem;                 // [2][2560] words
    uint32_t* sBp = (uint32_t*)(smem + 20480);       // [2][16384] words
    const uint32_t sB_base = smem_u32(sBp);

    const int tid  = threadIdx.x;
    const int lane = tid & 31;
    const int warp = tid >> 5;
    const int g    = lane >> 2;
    const int t4   = lane & 3;
    const int wr   = warp >> 3;     // 0..1
    const int wc   = warp & 7;      // 0..7 (owns cols wc*64..wc*64+63)

    const size_t rowbase = (size_t)blockIdx.x * 64;
    const float* xg = x + rowbase * 512;

    const int r_ = tid >> 3;             // 0..63
    const int c8 = (tid & 7) << 3;       // 0..56

    float acc[2][8][4];
#pragma unroll
    for (int mi = 0; mi < 2; mi++)
#pragma unroll
        for (int ni = 0; ni < 8; ni++)
#pragma unroll
            for (int e = 0; e < 4; e++) acc[mi][ni][e] = 0.0f;

    float4 av0, av1;

#define LDA(T) do { \
    av0 = *(const float4*)(xg + (size_t)r_ * 512 + (T) * 64 + c8); \
    av1 = *(const float4*)(xg + (size_t)r_ * 512 + (T) * 64 + c8 + 4); \
} while (0)

#define STA(S) do { \
    uint32_t* d_ = sAp + (S) * 2560 + r_ * 40 + ((c8 >> 4) << 3) + ((c8 >> 3) & 1); \
    d_[0] = h2pack(av0.x, av0.y); \
    d_[2] = h2pack(av0.z, av0.w); \
    d_[4] = h2pack(av1.x, av1.y); \
    d_[6] = h2pack(av1.z, av1.w); \
} while (0)

#define CPB(T, S) do { \
    const char* src_ = (const char*)g_WbF + (size_t)(T) * 65536 + tid * 16; \
    uint32_t dst_ = sB_base + (S) * 65536 + tid * 16; \
    _Pragma("unroll") \
    for (int i_ = 0; i_ < 8; i_++) \
        asm volatile("cp.async.cg.shared.global [%0], [%1], 16;" \
                     :: "r"(dst_ + i_ * 8192), "l"(src_ + i_ * 8192)); \
    asm volatile("cp.async.commit_group;" ::: "memory"); \
} while (0)

    // ---- prologue ----
    LDA(0);
    CPB(0, 0);
    STA(0);
    asm volatile("cp.async.wait_group 0;" ::: "memory");
    __syncthreads();

    // ---- mainloop: 8 double-buffered k-tiles of 64 ----
#pragma unroll 1
    for (int t = 0; t < 8; t++) {
        const int cur = t & 1, nxt = cur ^ 1;
        if (t < 7) {
            LDA(t + 1);
            CPB(t + 1, nxt);
        }
#pragma unroll
        for (int step = 0; step < 4; step++) {
            uint2 alo[2], ahi[2];
#pragma unroll
            for (int mi = 0; mi < 2; mi++) {
                const uint32_t* ap = sAp + cur * 2560 +
                    (wr * 32 + mi * 16 + g) * 40 + step * 8 + t4 * 2;
                alo[mi] = *(const uint2*)ap;
                ahi[mi] = *(const uint2*)(ap + 8 * 40);
            }
#pragma unroll
            for (int pi = 0; pi < 4; pi++) {
                uint4 bq = *(const uint4*)(sBp + cur * 16384 +
                    ((step * 32 + wc * 4 + pi) * 32 + lane) * 4);
#pragma unroll
                for (int mi = 0; mi < 2; mi++) {
                    mma16(acc[mi][2 * pi],     alo[mi].x, ahi[mi].x, alo[mi].y, ahi[mi].y, bq.x, bq.y);
                    mma16(acc[mi][2 * pi + 1], alo[mi].x, ahi[mi].x, alo[mi].y, ahi[mi].y, bq.z, bq.w);
                }
            }
        }
        if (t < 7) {
            STA(nxt);
            asm volatile("cp.async.wait_group 0;" ::: "memory");
        }
        __syncthreads();
    }

    // ======================= tail =======================
    uint32_t* B0 = (uint32_t*)smem;                  // 64 x PH words (half data)
    uint32_t* B1 = (uint32_t*)(smem + 18432);        // 128 x PH words
    float*    B2f = (float*)(smem + 55296);          // 64 x PTF f32

    const int twm = warp >> 3;
    const int twn = warp & 7;

    // S0: d1 -> B0 (wc 0,1); gate-i staging Y+bias -> B2f (wc 2,3); fc2_w -> B1
    if (wc < 2) {
#pragma unroll
        for (int mi = 0; mi < 2; mi++)
#pragma unroll
            for (int ni = 0; ni < 8; ni++) {
                int r = wr * 32 + mi * 16 + g;
                int cg = wc * 64 + ni * 8 + t4 * 2;
                int w0 = kword(cg);
                B0[r * PH + w0] = h2pack(fmaxf(acc[mi][ni][0] + fc1_b[cg], 0.f),
                                         fmaxf(acc[mi][ni][1] + fc1_b[cg + 1], 0.f));
                B0[(r + 8) * PH + w0] = h2pack(fmaxf(acc[mi][ni][2] + fc1_b[cg], 0.f),
                                               fmaxf(acc[mi][ni][3] + fc1_b[cg + 1], 0.f));
            }
    } else if (wc < 4) {
#pragma unroll
        for (int mi = 0; mi < 2; mi++)
#pragma unroll
            for (int ni = 0; ni < 8; ni++)
#pragma unroll
                for (int e = 0; e < 4; e++) {
                    int r = wr * 32 + mi * 16 + g + ((e >> 1) ? 8 : 0);
                    int cg = wc * 64 + ni * 8 + t4 * 2 + (e & 1);
                    int j = cg - 128;
                    B2f[r * PTF + j] = acc[mi][ni][e] + b_ih[j] + b_hh[j];
                }
    }
    for (int i = tid; i < 64 * 32; i += 512) {
        int r = i >> 5, c4 = (i & 31) << 2;
        float4 v = *(const float4*)(fc2_w + r * 128 + c4);
        int w0 = kword(c4);
        B1[r * PH + w0]     = h2pack(v.x, v.y);
        B1[r * PH + w0 + 2] = h2pack(v.z, v.w);
    }
    __syncthreads();

    // S1: G1 d2 = relu(d1 @ fc2_w.T + b)  K=128, N=64
    float tac1[2][1][4];
#pragma unroll
    for (int mi = 0; mi < 2; mi++)
#pragma unroll
        for (int e = 0; e < 4; e++) tac1[mi][0][e] = 0.f;
    tgemm_h<8, 1, PH, PH>(B0, B1, tac1, twm, twn, g, t4);
    __syncthreads();

    // S2: d2 -> B0 cols 0..63 ; fc3_w -> B1
    {
        int c = twn * 8 + t4 * 2;
        int w0 = kword(c);
#pragma unroll
        for (int mi = 0; mi < 2; mi++) {
            int r = twm * 32 + mi * 16 + g;
            B0[r * PH + w0] = h2pack(fmaxf(tac1[mi][0][0] + fc2_b[c], 0.f),
                                     fmaxf(tac1[mi][0][1] + fc2_b[c + 1], 0.f));
            B0[(r + 8) * PH + w0] = h2pack(fmaxf(tac1[mi][0][2] + fc2_b[c], 0.f),
                                           fmaxf(tac1[mi][0][3] + fc2_b[c + 1], 0.f));
        }
    }
    for (int i = tid; i < 128 * 16; i += 512) {
        int r = i >> 4, c4 = (i & 15) << 2;
        float4 v = *(const float4*)(fc3_w + r * 64 + c4);
        int w0 = kword(c4);
        B1[r * PH + w0]     = h2pack(v.x, v.y);
        B1[r * PH + w0 + 2] = h2pack(v.z, v.w);
    }
    __syncthreads();

    // S3: G2 d3 = d2 @ fc3_w.T + b  K=64, N=128
    float tac[2][2][4];
#pragma unroll
    for (int mi = 0; mi < 2; mi++)
#pragma unroll
        for (int ni = 0; ni < 2; ni++)
#pragma unroll
            for (int e = 0; e < 4; e++) tac[mi][ni][e] = 0.f;
    tgemm_h<4, 2, PH, PH>(B0, B1, tac, twm, twn, g, t4);
    __syncthreads();

    // S4: d3 -> B0 ; Wih_i -> B1
#pragma unroll
    for (int mi = 0; mi < 2; mi++)
#pragma unroll
        for (int ni = 0; ni < 2; ni++) {
            int r = twm * 32 + mi * 16 + g;
            int c = (twn * 2 + ni) * 8 + t4 * 2;
            int w0 = kword(c);
            B0[r * PH + w0] = h2pack(tac[mi][ni][0] + fc3_b[c],
                                     tac[mi][ni][1] + fc3_b[c + 1]);
            B0[(r + 8) * PH + w0] = h2pack(tac[mi][ni][2] + fc3_b[c],
                                           tac[mi][ni][3] + fc3_b[c + 1]);
        }
    for (int i = tid; i < 128 * 32; i += 512) {
        int r = i >> 5, c4 = (i & 31) << 2;
        float4 v = *(const float4*)(W_ih + (size_t)r * 640 + 512 + c4);
        int w0 = kword(c4);
        B1[r * PH + w0]     = h2pack(v.x, v.y);
        B1[r * PH + w0 + 2] = h2pack(v.z, v.w);
    }
    __syncthreads();

    // gates i, g, o
    float carry[2][2][4];
#pragma unroll 1
    for (int blk = 0; blk < 3; blk++) {
#pragma unroll
        for (int mi = 0; mi < 2; mi++)
#pragma unroll
            for (int ni = 0; ni < 2; ni++)
#pragma unroll
                for (int e = 0; e < 4; e++) tac[mi][ni][e] = 0.f;
        tgemm_h<8, 2, PH, PH>(B0, B1, tac, twm, twn, g, t4);
#pragma unroll
        for (int mi = 0; mi < 2; mi++)
#pragma unroll
            for (int ni = 0; ni < 2; ni++)
#pragma unroll
                for (int e = 0; e < 4; e++) {
                    int r = twm * 32 + mi * 16 + g + ((e >> 1) ? 8 : 0);
                    int j = (twn * 2 + ni) * 8 + t4 * 2 + (e & 1);
                    float v = tac[mi][ni][e] + B2f[r * PTF + j];
                    if (blk == 0)      carry[mi][ni][e] = v;
                    else if (blk == 1) carry[mi][ni][e] = sigm(carry[mi][ni][e]) * tanhf(v);
                    else               carry[mi][ni][e] = sigm(v) * tanhf(carry[mi][ni][e]);
                }
        __syncthreads();
        if (blk < 2) {
            const int wlo = 4 + 2 * blk;
            const int boff = (blk == 0) ? 256 : 384;
            if (wc == wlo || wc == wlo + 1) {
#pragma unroll
                for (int mi = 0; mi < 2; mi++)
#pragma unroll
                    for (int ni = 0; ni < 8; ni++)
#pragma unroll
                        for (int e = 0; e < 4; e++) {
                            int r = wr * 32 + mi * 16 + g + ((e >> 1) ? 8 : 0);
                            int cg = wc * 64 + ni * 8 + t4 * 2 + (e & 1);
                            int j = cg - (blk + 2) * 128;
                            B2f[r * PTF + j] = acc[mi][ni][e] + b_ih[boff + j] + b_hh[boff + j];
                        }
            }
            const int wrow = (blk == 0) ? 256 : 384;
            for (int i = tid; i < 128 * 32; i += 512) {
                int r = i >> 5, c4 = (i & 31) << 2;
                float4 v = *(const float4*)(W_ih + (size_t)(wrow + r) * 640 + 512 + c4);
                int w0 = kword(c4);
                B1[r * PH + w0]     = h2pack(v.x, v.y);
                B1[r * PH + w0 + 2] = h2pack(v.z, v.w);
            }
        } else {
            // h -> B0 ; fc_w -> B1
#pragma unroll
            for (int mi = 0; mi < 2; mi++)
#pragma unroll
                for (int ni = 0; ni < 2; ni++) {
                    int r = twm * 32 + mi * 16 + g;
                    int c = (twn * 2 + ni) * 8 + t4 * 2;
                    int w0 = kword(c);
                    B0[r * PH + w0] = h2pack(carry[mi][ni][0], carry[mi][ni][1]);
                    B0[(r + 8) * PH + w0] = h2pack(carry[mi][ni][2], carry[mi][ni][3]);
                }
            for (int i = tid; i < 128 * 32; i += 512) {
                int r = i >> 5, c4 = (i & 31) << 2;
                float4 v = *(const float4*)(fc_w + r * 128 + c4);
                int w0 = kword(c4);
                B1[r * PH + w0]     = h2pack(v.x, v.y);
                B1[r * PH + w0 + 2] = h2pack(v.z, v.w);
            }
        }
        __syncthreads();
    }

    // G4: out = h @ fc_w.T + fc_b
#pragma unroll
    for (int mi = 0; mi < 2; mi++)
#pragma unroll
        for (int ni = 0; ni < 2; ni++)
#pragma unroll
            for (int e = 0; e < 4; e++) tac[mi][ni][e] = 0.f;
    tgemm_h<8, 2, PH, PH>(B0, B1, tac, twm, twn, g, t4);
#pragma unroll
    for (int mi = 0; mi < 2; mi++)
#pragma unroll
        for (int ni = 0; ni < 2; ni++) {
            int r = twm * 32 + mi * 16 + g;
            int c = (twn * 2 + ni) * 8 + t4 * 2;
            *(float2*)(out + (rowbase + r) * 128 + c) =
                make_float2(tac[mi][ni][0] + fc_b[c], tac[mi][ni][1] + fc_b[c + 1]);
            *(float2*)(out + (rowbase + r + 8) * 128 + c) =
                make_float2(tac[mi][ni][2] + fc_b[c], tac[mi][ni][3] + fc_b[c + 1]);
        }
#undef LDA
#undef STA
#undef CPB
}

// ---------------------------------------------------------------------------
extern "C" void kernel_launch(void* const* d_in, const int* in_sizes, int n_in,
                              void* d_out, int out_size) {
    const float* x     = (const float*)d_in[0];
    const float* fc1_w = (const float*)d_in[1];
    const float* fc1_b = (const float*)d_in[2];
    const float* fc2_w = (const float*)d_in[3];
    const float* fc2_b = (const float*)d_in[4];
    const float* fc3_w = (const float*)d_in[5];
    const float* fc3_b = (const float*)d_in[6];
    const float* W_ih  = (const float*)d_in[7];
    // d_in[8] = W_hh (dead: h_prev == 0)
    const float* b_ih  = (const float*)d_in[9];
    const float* b_hh  = (const float*)d_in[10];
    // d_in[11..12] = attn_w, attn_b (dead: softmax over length-1 seq == 1)
    const float* fc_w  = (const float*)d_in[13];
    const float* fc_b  = (const float*)d_in[14];
    float* out = (float*)d_out;

    const int smem = 151552;
    cudaFuncSetAttribute(fused_kernel, cudaFuncAttributeMaxDynamicSharedMemorySize, smem);

    pack_kernel<<<512, 256>>>(fc1_w, W_ih);
    fused_kernel<<<NROWS / 64, 512, smem>>>(x, fc1_b, fc2_w, fc2_b, fc3_w, fc3_b,
                                            W_ih, b_ih, b_hh, fc_w, fc_b, out);
}

// round 11
// speedup vs baseline: 3.2094x; 1.9650x over previous
#include <cuda_runtime.h>
#include <cuda_fp16.h>
#include <cstdint>

// ===========================================================================
// DNN+LSTM fused, fp16 mma.sync.m16n8k16 (f32 acc). Tail rebuilt:
//  - all tail weights pre-packed to fp16 smem-image layout in global
//  - tail weight buffers double-buffered ABOVE mainloop smem, cp.async
//    prefetch pipelined (fc2/fc3 arrive during the mainloop)
//  - gate pre-activations staged once; branchless approx activations
//   Y[B,512] = x @ Wb.T (Wb=[fc1_w; W_ih(i,g,o)[:,:512]])
//   d1=relu(Y0+b); d2=relu(d1@fc2.T+b); d3=d2@fc3.T+b
//   i/g/o = Ygate + d3@Wih[:,512:].T + b; c=sig(i)tanh(g); h=sig(o)tanh(c)
//   out = h @ fc_w.T + fc_b    (f-gate, W_hh, attention dead)
// ===========================================================================

#define NROWS 131072
#define PTF 396    // f32 gate-staging pitch (words), 396%32==12 -> conflict-free
#define PH 72      // fp16 tail row pitch (32-bit words)

// Mainloop B: fp16 ni-paired fragment layout, 8 tiles x 64KB (as R8)
__device__ __align__(1024) uint32_t g_WbF[131072];
// Tail weight images (fp16, PH-pitch rows = exact smem image):
//  [0]=fc2(64r), [4608]=fc3(128r), [13824]=Wi, [23040]=Wg, [32256]=Wo, [41472]=fcw
__device__ __align__(1024) uint32_t g_WtF[50688];

__device__ __forceinline__ uint32_t h2pack(float a, float b) {
    __half2 h = __floats2half2_rn(a, b);
    return *reinterpret_cast<uint32_t*>(&h);
}
__device__ __forceinline__ void mma16(float* c, uint32_t a0, uint32_t a1,
                                      uint32_t a2, uint32_t a3,
                                      uint32_t b0, uint32_t b1) {
    asm volatile(
        "mma.sync.aligned.m16n8k16.row.col.f32.f16.f16.f32 "
        "{%0,%1,%2,%3},{%4,%5,%6,%7},{%8,%9},{%0,%1,%2,%3};"
        : "+f"(c[0]), "+f"(c[1]), "+f"(c[2]), "+f"(c[3])
        : "r"(a0), "r"(a1), "r"(a2), "r"(a3), "r"(b0), "r"(b1));
}
// branchless approx activations (ex2/rcp: ~1-2 ulp, << fp16 noise)
__device__ __forceinline__ float fsigm(float x) {
    float t = -1.442695041f * x, e, r;
    asm("ex2.approx.f32 %0, %1;" : "=f"(e) : "f"(t));
    float d = 1.0f + e;
    asm("rcp.approx.f32 %0, %1;" : "=f"(r) : "f"(d));
    return r;
}
__device__ __forceinline__ float ftanhA(float x) {
    return fmaf(2.0f, fsigm(2.0f * x), -1.0f);
}
__device__ __forceinline__ uint32_t smem_u32(const void* p) {
    return (uint32_t)__cvta_generic_to_shared(p);
}
__device__ __forceinline__ int kword(int k) {
    int kk = k & 15;
    return (k >> 4) * 8 + ((kk & 7) >> 1) * 2 + ((kk >> 3) & 1);
}

// ---------------------------------------------------------------------------
__global__ void pack_kernel(const float* __restrict__ fc1_w,
                            const float* __restrict__ fc2_w,
                            const float* __restrict__ fc3_w,
                            const float* __restrict__ W_ih,
                            const float* __restrict__ fc_w) {
    int w = blockIdx.x * 256 + threadIdx.x;
    if (w >= 131072 + 50688) return;
    if (w < 131072) {
        int tile = w >> 14;
        int rem  = w & 16383;
        int step = rem >> 12;
        int p    = (rem >> 7) & 31;
        int lane = (rem >> 2) & 31;
        int q    = rem & 3;
        int n = (2 * p + (q >> 1)) * 8 + (lane >> 2);
        int k = tile * 64 + step * 16 + 2 * (lane & 3) + 8 * (q & 1);
        float v0, v1;
        if (n < 128) { v0 = fc1_w[n * 512 + k]; v1 = fc1_w[n * 512 + k + 1]; }
        else {
            int sr = (n < 256) ? n - 128 : n;
            v0 = W_ih[(size_t)sr * 640 + k]; v1 = W_ih[(size_t)sr * 640 + k + 1];
        }
        g_WbF[w] = h2pack(v0, v1);
    } else {
        int t = w - 131072;
        int img, base;
        if (t < 4608)       { img = 0; base = t; }
        else if (t < 13824) { img = 1; base = t - 4608; }
        else if (t < 23040) { img = 2; base = t - 13824; }
        else if (t < 32256) { img = 3; base = t - 23040; }
        else if (t < 41472) { img = 4; base = t - 32256; }
        else                { img = 5; base = t - 41472; }
        int n = base / 72, ww = base % 72;
        const float* src; int kc;
        switch (img) {
            case 0:  src = fc2_w + n * 128;                        kc = 128; break;
            case 1:  src = fc3_w + n * 64;                         kc = 64;  break;
            case 2:  src = W_ih + (size_t)n * 640 + 512;           kc = 128; break;
            case 3:  src = W_ih + (size_t)(256 + n) * 640 + 512;   kc = 128; break;
            case 4:  src = W_ih + (size_t)(384 + n) * 640 + 512;   kc = 128; break;
            default: src = fc_w + n * 128;                         kc = 128; break;
        }
        uint32_t val = 0;
        if (ww < (kc >> 1)) {
            int j = ww & 7;
            int k = (ww >> 3) * 16 + (j & 1) * 8 + (j >> 1) * 2;
            val = h2pack(src[k], src[k + 1]);
        }
        g_WtF[t] = val;
    }
}

// ---------------------------------------------------------------------------
// tail GEMM (fp16, permuted rows). 16 warps: twm=warp>>3, twn=warp&7
// ---------------------------------------------------------------------------
template <int KSTEPS, int NT>
__device__ __forceinline__ void tgemm_h(const uint32_t* __restrict__ sAa,
                                        const uint32_t* __restrict__ sW,
                                        float tac[2][NT][4],
                                        int twm, int twn, int g, int t4) {
#pragma unroll
    for (int s = 0; s < KSTEPS; s++) {
        uint2 alo[2], ahi[2];
#pragma unroll
        for (int mi = 0; mi < 2; mi++) {
            const uint32_t* ap = sAa + (twm * 32 + mi * 16 + g) * PH + s * 8 + t4 * 2;
            alo[mi] = *(const uint2*)ap;
            ahi[mi] = *(const uint2*)(ap + 8 * PH);
        }
#pragma unroll
        for (int ni = 0; ni < NT; ni++) {
            int n = (twn * NT + ni) * 8 + g;
            uint2 b = *(const uint2*)(sW + n * PH + s * 8 + t4 * 2);
#pragma unroll
            for (int mi = 0; mi < 2; mi++)
                mma16(tac[mi][ni], alo[mi].x, ahi[mi].x, alo[mi].y, ahi[mi].y, b.x, b.y);
        }
    }
}

// ---------------------------------------------------------------------------
// smem map: mainloop sA [2][2560]w @0 (20480B), sB [2][16384]w @20480 (131072B)
// tail (aliased low): B0h @0 (64x72w=18432B), B2f @18432 (64x396 f32=101376B)
// tail weight dbl-buf (disjoint, above mainloop): B1a @151552, B1b @188416
// total = 225280
// ---------------------------------------------------------------------------
__global__ __launch_bounds__(512, 1) void fused_kernel(
    const float* __restrict__ x,
    const float* __restrict__ fc1_b, const float* __restrict__ fc2_b,
    const float* __restrict__ fc3_b, const float* __restrict__ b_ih,
    const float* __restrict__ b_hh,  const float* __restrict__ fc_b,
    float* __restrict__ out) {
    extern __shared__ char smem[];
    uint32_t* sAp = (uint32_t*)smem;
    uint32_t* sBp = (uint32_t*)(smem + 20480);
    const uint32_t sbase = smem_u32(smem);
    const uint32_t sB_base = sbase + 20480;
    const uint32_t B1A_s = sbase + 151552;
    const uint32_t B1B_s = sbase + 188416;
    uint32_t* B1a = (uint32_t*)(smem + 151552);
    uint32_t* B1b = (uint32_t*)(smem + 188416);

    const int tid  = threadIdx.x;
    const int lane = tid & 31;
    const int warp = tid >> 5;
    const int g    = lane >> 2;
    const int t4   = lane & 3;
    const int wr   = warp >> 3;     // 0..1
    const int wc   = warp & 7;      // 0..7

    const size_t rowbase = (size_t)blockIdx.x * 64;
    const float* xg = x + rowbase * 512;

    const int r_ = tid >> 3;
    const int c8 = (tid & 7) << 3;

    float acc[2][8][4];
#pragma unroll
    for (int mi = 0; mi < 2; mi++)
#pragma unroll
        for (int ni = 0; ni < 8; ni++)
#pragma unroll
            for (int e = 0; e < 4; e++) acc[mi][ni][e] = 0.0f;

    float4 av0, av1;

#define LDA(T) do { \
    av0 = *(const float4*)(xg + (size_t)r_ * 512 + (T) * 64 + c8); \
    av1 = *(const float4*)(xg + (size_t)r_ * 512 + (T) * 64 + c8 + 4); \
} while (0)

#define STA(S) do { \
    uint32_t* d_ = sAp + (S) * 2560 + r_ * 40 + ((c8 >> 4) << 3) + ((c8 >> 3) & 1); \
    d_[0] = h2pack(av0.x, av0.y); \
    d_[2] = h2pack(av0.z, av0.w); \
    d_[4] = h2pack(av1.x, av1.y); \
    d_[6] = h2pack(av1.z, av1.w); \
} while (0)

#define CPB(T, S) do { \
    const char* src_ = (const char*)g_WbF + (size_t)(T) * 65536 + tid * 16; \
    uint32_t dst_ = sB_base + (S) * 65536 + tid * 16; \
    _Pragma("unroll") \
    for (int i_ = 0; i_ < 8; i_++) \
        asm volatile("cp.async.cg.shared.global [%0], [%1], 16;" \
                     :: "r"(dst_ + i_ * 8192), "l"(src_ + i_ * 8192)); \
    asm volatile("cp.async.commit_group;" ::: "memory"); \
} while (0)

#define FILLW(imgoff_w, bytes, dst_s) do { \
    const char* s_ = (const char*)g_WtF + (size_t)(imgoff_w) * 4; \
    for (int o_ = tid * 16; o_ < (bytes); o_ += 8192) \
        asm volatile("cp.async.cg.shared.global [%0], [%1], 16;" \
                     :: "r"((dst_s) + o_), "l"(s_ + o_)); \
    asm volatile("cp.async.commit_group;" ::: "memory"); \
} while (0)

    // ---- prologue: tile-0 B + A, plus fc2/fc3 tail prefetch (hidden) ----
    LDA(0);
    CPB(0, 0);
    FILLW(0, 18432, B1A_s);       // fc2
    FILLW(4608, 36864, B1B_s);    // fc3
    STA(0);
    asm volatile("cp.async.wait_group 2;" ::: "memory");  // tile-0 B only
    __syncthreads();

    // ---- mainloop: 8 double-buffered k-tiles of 64 ----
#pragma unroll 1
    for (int t = 0; t < 8; t++) {
        const int cur = t & 1, nxt = cur ^ 1;
        if (t < 7) {
            LDA(t + 1);
            CPB(t + 1, nxt);
        }
#pragma unroll
        for (int step = 0; step < 4; step++) {
            uint2 alo[2], ahi[2];
#pragma unroll
            for (int mi = 0; mi < 2; mi++) {
                const uint32_t* ap = sAp + cur * 2560 +
                    (wr * 32 + mi * 16 + g) * 40 + step * 8 + t4 * 2;
                alo[mi] = *(const uint2*)ap;
                ahi[mi] = *(const uint2*)(ap + 8 * 40);
            }
#pragma unroll
            for (int pi = 0; pi < 4; pi++) {
                uint4 bq = *(const uint4*)(sBp + cur * 16384 +
                    ((step * 32 + wc * 4 + pi) * 32 + lane) * 4);
#pragma unroll
                for (int mi = 0; mi < 2; mi++) {
                    mma16(acc[mi][2 * pi],     alo[mi].x, ahi[mi].x, alo[mi].y, ahi[mi].y, bq.x, bq.y);
                    mma16(acc[mi][2 * pi + 1], alo[mi].x, ahi[mi].x, alo[mi].y, ahi[mi].y, bq.z, bq.w);
                }
            }
        }
        if (t < 7) {
            STA(nxt);
            asm volatile("cp.async.wait_group 0;" ::: "memory");
        }
        __syncthreads();
    }

    // ======================= tail =======================
    uint32_t* B0  = (uint32_t*)smem;            // 64 x PH (fp16 data)
    float*    B2f = (float*)(smem + 18432);     // 64 x PTF f32 (gate preacts)

    const int twm = wr;
    const int twn = wc;

    // ---- S0: d1 -> B0 (wc 0,1); ALL gate preacts Y+bias -> B2f (wc 2..7) ----
    if (wc < 2) {
#pragma unroll
        for (int mi = 0; mi < 2; mi++)
#pragma unroll
            for (int ni = 0; ni < 8; ni++) {
                int r = wr * 32 + mi * 16 + g;
                int cg = wc * 64 + ni * 8 + t4 * 2;
                int w0 = kword(cg);
                B0[r * PH + w0] = h2pack(fmaxf(acc[mi][ni][0] + fc1_b[cg], 0.f),
                                         fmaxf(acc[mi][ni][1] + fc1_b[cg + 1], 0.f));
                B0[(r + 8) * PH + w0] = h2pack(fmaxf(acc[mi][ni][2] + fc1_b[cg], 0.f),
                                               fmaxf(acc[mi][ni][3] + fc1_b[cg + 1], 0.f));
            }
    } else {
#pragma unroll
        for (int mi = 0; mi < 2; mi++)
#pragma unroll
            for (int ni = 0; ni < 8; ni++)
#pragma unroll
                for (int e = 0; e < 4; e++) {
                    int r = wr * 32 + mi * 16 + g + ((e >> 1) ? 8 : 0);
                    int cg = wc * 64 + ni * 8 + t4 * 2 + (e & 1);
                    int bi = (cg < 256) ? cg - 128 : cg;   // i:0.. g:256.. o:384..
                    B2f[r * PTF + (cg - 128)] = acc[mi][ni][e] + b_ih[bi] + b_hh[bi];
                }
    }
    __syncthreads();

    // ---- G1: d2 = relu(d1 @ fc2.T + b)   [B1a = fc2, arrived in mainloop] ----
    float tac1[2][1][4];
#pragma unroll
    for (int mi = 0; mi < 2; mi++)
#pragma unroll
        for (int e = 0; e < 4; e++) tac1[mi][0][e] = 0.f;
    tgemm_h<8, 1>(B0, B1a, tac1, twm, twn, g, t4);
    __syncthreads();
    {   // store d2 -> B0 cols 0..63 ; prefetch Wi -> B1a
        int c = twn * 8 + t4 * 2;
        int w0 = kword(c);
#pragma unroll
        for (int mi = 0; mi < 2; mi++) {
            int r = twm * 32 + mi * 16 + g;
            B0[r * PH + w0] = h2pack(fmaxf(tac1[mi][0][0] + fc2_b[c], 0.f),
                                     fmaxf(tac1[mi][0][1] + fc2_b[c + 1], 0.f));
            B0[(r + 8) * PH + w0] = h2pack(fmaxf(tac1[mi][0][2] + fc2_b[c], 0.f),
                                           fmaxf(tac1[mi][0][3] + fc2_b[c + 1], 0.f));
        }
    }
    FILLW(13824, 36864, B1A_s);   // Wi
    __syncthreads();

    // ---- G2: d3 = d2 @ fc3.T + b   [B1b = fc3] ----
    float tac[2][2][4];
#pragma unroll
    for (int mi = 0; mi < 2; mi++)
#pragma unroll
        for (int ni = 0; ni < 2; ni++)
#pragma unroll
            for (int e = 0; e < 4; e++) tac[mi][ni][e] = 0.f;
    tgemm_h<4, 2>(B0, B1b, tac, twm, twn, g, t4);
    __syncthreads();
    // store d3 -> B0 ; prefetch Wg -> B1b ; ensure Wi done
#pragma unroll
    for (int mi = 0; mi < 2; mi++)
#pragma unroll
        for (int ni = 0; ni < 2; ni++) {
            int r = twm * 32 + mi * 16 + g;
            int c = (twn * 2 + ni) * 8 + t4 * 2;
            int w0 = kword(c);
            B0[r * PH + w0] = h2pack(tac[mi][ni][0] + fc3_b[c],
                                     tac[mi][ni][1] + fc3_b[c + 1]);
            B0[(r + 8) * PH + w0] = h2pack(tac[mi][ni][2] + fc3_b[c],
                                           tac[mi][ni][3] + fc3_b[c + 1]);
        }
    FILLW(23040, 36864, B1B_s);   // Wg
    asm volatile("cp.async.wait_group 1;" ::: "memory");
    __syncthreads();

    // ---- gate i: si = sigm(d3 @ Wi.T + preact_i)   [B1a = Wi] ----
    float si[2][2][4];
    {
        float tg[2][2][4];
#pragma unroll
        for (int mi = 0; mi < 2; mi++)
#pragma unroll
            for (int ni = 0; ni < 2; ni++)
#pragma unroll
                for (int e = 0; e < 4; e++) tg[mi][ni][e] = 0.f;
        tgemm_h<8, 2>(B0, B1a, tg, twm, twn, g, t4);
#pragma unroll
        for (int mi = 0; mi < 2; mi++)
#pragma unroll
            for (int ni = 0; ni < 2; ni++)
#pragma unroll
                for (int e = 0; e < 4; e++) {
                    int r = twm * 32 + mi * 16 + g + ((e >> 1) ? 8 : 0);
                    int j = (twn * 2 + ni) * 8 + t4 * 2 + (e & 1);
                    si[mi][ni][e] = fsigm(tg[mi][ni][e] + B2f[r * PTF + j]);
                }
    }
    __syncthreads();
    FILLW(32256, 36864, B1A_s);   // Wo
    asm volatile("cp.async.wait_group 1;" ::: "memory");
    __syncthreads();

    // ---- gate g: c = si * tanh(d3 @ Wg.T + preact_g)   [B1b = Wg] ----
    float cc[2][2][4];
    {
        float tg[2][2][4];
#pragma unroll
        for (int mi = 0; mi < 2; mi++)
#pragma unroll
            for (int ni = 0; ni < 2; ni++)
#pragma unroll
                for (int e = 0; e < 4; e++) tg[mi][ni][e] = 0.f;
        tgemm_h<8, 2>(B0, B1b, tg, twm, twn, g, t4);
#pragma unroll
        for (int mi = 0; mi < 2; mi++)
#pragma unroll
            for (int ni = 0; ni < 2; ni++)
#pragma unroll
                for (int e = 0; e < 4; e++) {
                    int r = twm * 32 + mi * 16 + g + ((e >> 1) ? 8 : 0);
                    int j = (twn * 2 + ni) * 8 + t4 * 2 + (e & 1);
                    cc[mi][ni][e] = si[mi][ni][e] *
                                    ftanhA(tg[mi][ni][e] + B2f[r * PTF + 128 + j]);
                }
    }
    __syncthreads();
    FILLW(41472, 36864, B1B_s);   // fc_w
    asm volatile("cp.async.wait_group 1;" ::: "memory");
    __syncthreads();

    // ---- gate o: h = sigm(d3 @ Wo.T + preact_o) * tanh(c)   [B1a = Wo] ----
    float hh[2][2][4];
    {
        float tg[2][2][4];
#pragma unroll
        for (int mi = 0; mi < 2; mi++)
#pragma unroll
            for (int ni = 0; ni < 2; ni++)
#pragma unroll
                for (int e = 0; e < 4; e++) tg[mi][ni][e] = 0.f;
        tgemm_h<8, 2>(B0, B1a, tg, twm, twn, g, t4);
#pragma unroll
        for (int mi = 0; mi < 2; mi++)
#pragma unroll
            for (int ni = 0; ni < 2; ni++)
#pragma unroll
                for (int e = 0; e < 4; e++) {
                    int r = twm * 32 + mi * 16 + g + ((e >> 1) ? 8 : 0);
                    int j = (twn * 2 + ni) * 8 + t4 * 2 + (e & 1);
                    hh[mi][ni][e] = fsigm(tg[mi][ni][e] + B2f[r * PTF + 256 + j]) *
                                    ftanhA(cc[mi][ni][e]);
                }
    }
    __syncthreads();
    // store h -> B0 (fp16) ; ensure fc_w arrived
#pragma unroll
    for (int mi = 0; mi < 2; mi++)
#pragma unroll
        for (int ni = 0; ni < 2; ni++) {
            int r = twm * 32 + mi * 16 + g;
            int c = (twn * 2 + ni) * 8 + t4 * 2;
            int w0 = kword(c);
            B0[r * PH + w0] = h2pack(hh[mi][ni][0], hh[mi][ni][1]);
            B0[(r + 8) * PH + w0] = h2pack(hh[mi][ni][2], hh[mi][ni][3]);
        }
    asm volatile("cp.async.wait_group 0;" ::: "memory");
    __syncthreads();

    // ---- G4: out = h @ fc_w.T + fc_b   [B1b = fc_w] ----
#pragma unroll
    for (int mi = 0; mi < 2; mi++)
#pragma unroll
        for (int ni = 0; ni < 2; ni++)
#pragma unroll
            for (int e = 0; e < 4; e++) tac[mi][ni][e] = 0.f;
    tgemm_h<8, 2>(B0, B1b, tac, twm, twn, g, t4);
#pragma unroll
    for (int mi = 0; mi < 2; mi++)
#pragma unroll
        for (int ni = 0; ni < 2; ni++) {
            int r = twm * 32 + mi * 16 + g;
            int c = (twn * 2 + ni) * 8 + t4 * 2;
            *(float2*)(out + (rowbase + r) * 128 + c) =
                make_float2(tac[mi][ni][0] + fc_b[c], tac[mi][ni][1] + fc_b[c + 1]);
            *(float2*)(out + (rowbase + r + 8) * 128 + c) =
                make_float2(tac[mi][ni][2] + fc_b[c], tac[mi][ni][3] + fc_b[c + 1]);
        }
#undef LDA
#undef STA
#undef CPB
#undef FILLW
}

// ---------------------------------------------------------------------------
extern "C" void kernel_launch(void* const* d_in, const int* in_sizes, int n_in,
                              void* d_out, int out_size) {
    const float* x     = (const float*)d_in[0];
    const float* fc1_w = (const float*)d_in[1];
    const float* fc1_b = (const float*)d_in[2];
    const float* fc2_w = (const float*)d_in[3];
    const float* fc2_b = (const float*)d_in[4];
    const float* fc3_w = (const float*)d_in[5];
    const float* fc3_b = (const float*)d_in[6];
    const float* W_ih  = (const float*)d_in[7];
    // d_in[8] = W_hh (dead: h_prev == 0)
    const float* b_ih  = (const float*)d_in[9];
    const float* b_hh  = (const float*)d_in[10];
    // d_in[11..12] = attn_w, attn_b (dead: softmax over length-1 seq == 1)
    const float* fc_w  = (const float*)d_in[13];
    const float* fc_b  = (const float*)d_in[14];
    float* out = (float*)d_out;

    const int smem = 225280;
    cudaFuncSetAttribute(fused_kernel, cudaFuncAttributeMaxDynamicSharedMemorySize, smem);

    pack_kernel<<<710, 256>>>(fc1_w, fc2_w, fc3_w, W_ih, fc_w);
    fused_kernel<<<NROWS / 64, 512, smem>>>(x, fc1_b, fc2_b, fc3_b,
                                            b_ih, b_hh, fc_b, out);
}

// round 12
// speedup vs baseline: 3.2325x; 1.0072x over previous
#include <cuda_runtime.h>
#include <cuda_fp16.h>
#include <cstdint>

// ===========================================================================
// DNN+LSTM fused, fp16 mma.sync.m16n8k16 (f32 acc).
//  - mainloop: Y = x @ Wb.T, 8 double-buffered k64 tiles (unchanged from R11)
//  - tail: merged i/g/o gate GEMM (N=384, one pass), fp16 preact staging,
//    all weights resident via early cp.async commits; 7 barriers total.
//   Y[B,512] = x @ Wb.T (Wb=[fc1_w; W_ih(i,g,o)[:,:512]])
//   d1=relu(Y0+b); d2=relu(d1@fc2.T+b); d3=d2@fc3.T+b
//   i/g/o = Ygate + d3@Wih[:,512:].T + b; c=sig(i)tanh(g); h=sig(o)tanh(c)
//   out = h @ fc_w.T + fc_b    (f-gate, W_hh, attention dead)
// ===========================================================================

#define NROWS 131072
#define PH 72      // fp16 row pitch (32-bit words), 72%32==8 -> conflict-free
#define PF3 40     // fc3 row pitch (K=64)
#define PB2 196    // preact half2 pitch (words), 196%32==4 -> conflict-free

// Mainloop B: fp16 ni-paired fragment layout, 8 tiles x 64KB
__device__ __align__(1024) uint32_t g_WbF[131072];
// Tail weight images (fp16 fragment rows):
//  [0]=fc2 (64x72), [4608]=fc3 (128x40), [9728]=Wigo (384x72, gate-interleaved),
//  [37376]=fcw (128x72)   -> 46592 words
__device__ __align__(1024) uint32_t g_WtF[46592];

__device__ __forceinline__ uint32_t h2pack(float a, float b) {
    __half2 h = __floats2half2_rn(a, b);
    return *reinterpret_cast<uint32_t*>(&h);
}
__device__ __forceinline__ void mma16(float* c, uint32_t a0, uint32_t a1,
                                      uint32_t a2, uint32_t a3,
                                      uint32_t b0, uint32_t b1) {
    asm volatile(
        "mma.sync.aligned.m16n8k16.row.col.f32.f16.f16.f32 "
        "{%0,%1,%2,%3},{%4,%5,%6,%7},{%8,%9},{%0,%1,%2,%3};"
        : "+f"(c[0]), "+f"(c[1]), "+f"(c[2]), "+f"(c[3])
        : "r"(a0), "r"(a1), "r"(a2), "r"(a3), "r"(b0), "r"(b1));
}
__device__ __forceinline__ float fsigm(float x) {
    float t = -1.442695041f * x, e, r;
    asm("ex2.approx.f32 %0, %1;" : "=f"(e) : "f"(t));
    float d = 1.0f + e;
    asm("rcp.approx.f32 %0, %1;" : "=f"(r) : "f"(d));
    return r;
}
__device__ __forceinline__ float ftanhA(float x) {
    return fmaf(2.0f, fsigm(2.0f * x), -1.0f);
}
__device__ __forceinline__ uint32_t smem_u32(const void* p) {
    return (uint32_t)__cvta_generic_to_shared(p);
}
__device__ __forceinline__ int kword(int k) {
    int kk = k & 15;
    return (k >> 4) * 8 + ((kk & 7) >> 1) * 2 + ((kk >> 3) & 1);
}

// ---------------------------------------------------------------------------
__global__ void pack_kernel(const float* __restrict__ fc1_w,
                            const float* __restrict__ fc2_w,
                            const float* __restrict__ fc3_w,
                            const float* __restrict__ W_ih,
                            const float* __restrict__ fc_w) {
    int w = blockIdx.x * 256 + threadIdx.x;
    if (w >= 131072 + 46592) return;
    if (w < 131072) {
        int tile = w >> 14;
        int rem  = w & 16383;
        int step = rem >> 12;
        int p    = (rem >> 7) & 31;
        int lane = (rem >> 2) & 31;
        int q    = rem & 3;
        int n = (2 * p + (q >> 1)) * 8 + (lane >> 2);
        int k = tile * 64 + step * 16 + 2 * (lane & 3) + 8 * (q & 1);
        float v0, v1;
        if (n < 128) { v0 = fc1_w[n * 512 + k]; v1 = fc1_w[n * 512 + k + 1]; }
        else {
            int sr = (n < 256) ? n - 128 : n;
            v0 = W_ih[(size_t)sr * 640 + k]; v1 = W_ih[(size_t)sr * 640 + k + 1];
        }
        g_WbF[w] = h2pack(v0, v1);
        return;
    }
    int t = w - 131072;
    const float* src = nullptr;
    int ww, kc;
    if (t < 4608) {                       // fc2: 64 rows, K=128, pitch 72
        int n = t / 72; ww = t % 72; kc = 128;
        src = fc2_w + n * 128;
    } else if (t < 9728) {                // fc3: 128 rows, K=64, pitch 40
        int t2 = t - 4608;
        int n = t2 / 40; ww = t2 % 40; kc = 64;
        src = fc3_w + n * 64;
    } else if (t < 37376) {               // Wigo: 384 rows, K=128, pitch 72
        int t2 = t - 9728;
        int p = t2 / 72; ww = t2 % 72; kc = 128;
        int twn_p = p / 48, rem = p % 48;
        int nip = rem >> 3, jg = rem & 7;
        int gate = nip >> 1, ni = nip & 1;
        int c = twn_p * 16 + ni * 8 + jg;
        int base = (gate == 0) ? 0 : (gate == 1) ? 256 : 384;
        src = W_ih + (size_t)(base + c) * 640 + 512;
    } else {                              // fcw: 128 rows, K=128, pitch 72
        int t2 = t - 37376;
        int n = t2 / 72; ww = t2 % 72; kc = 128;
        src = fc_w + n * 128;
    }
    uint32_t val = 0;
    if (ww < (kc >> 1)) {
        int j = ww & 7;
        int k = (ww >> 3) * 16 + (j & 1) * 8 + (j >> 1) * 2;
        val = h2pack(src[k], src[k + 1]);
    }
    g_WtF[t] = val;
}

// ---------------------------------------------------------------------------
// tail GEMM (fp16, permuted rows). 16 warps: twm=warp>>3, twn=warp&7
// ---------------------------------------------------------------------------
template <int KSTEPS, int NT, int PA_, int PW_>
__device__ __forceinline__ void tgemm_h(const uint32_t* __restrict__ sAa,
                                        const uint32_t* __restrict__ sW,
                                        float tac[2][NT][4],
                                        int twm, int twn, int g, int t4) {
#pragma unroll
    for (int s = 0; s < KSTEPS; s++) {
        uint2 alo[2], ahi[2];
#pragma unroll
        for (int mi = 0; mi < 2; mi++) {
            const uint32_t* ap = sAa + (twm * 32 + mi * 16 + g) * PA_ + s * 8 + t4 * 2;
            alo[mi] = *(const uint2*)ap;
            ahi[mi] = *(const uint2*)(ap + 8 * PA_);
        }
#pragma unroll
        for (int ni = 0; ni < NT; ni++) {
            int n = (twn * NT + ni) * 8 + g;
            uint2 b = *(const uint2*)(sW + n * PW_ + s * 8 + t4 * 2);
#pragma unroll
            for (int mi = 0; mi < 2; mi++)
                mma16(tac[mi][ni], alo[mi].x, ahi[mi].x, alo[mi].y, ahi[mi].y, b.x, b.y);
        }
    }
}

// ---------------------------------------------------------------------------
// smem (total 232448):
//  mainloop: sA [0,20480), sB [20480,151552)
//  prefetch during mainloop: fc2 @193536 (18432), fc3 @211968 (20480)
//  tail: B0 @0 (18432), B2H @18432 (50176), Wigo @68608 (110592, filled @S0),
//        fcw @179200 (36864, filled post-G2; overlays dead fc2/fc3 tail)
// ---------------------------------------------------------------------------
__global__ __launch_bounds__(512, 1) void fused_kernel(
    const float* __restrict__ x,
    const float* __restrict__ fc1_b, const float* __restrict__ fc2_b,
    const float* __restrict__ fc3_b, const float* __restrict__ b_ih,
    const float* __restrict__ b_hh,  const float* __restrict__ fc_b,
    float* __restrict__ out) {
    extern __shared__ char smem[];
    uint32_t* sAp = (uint32_t*)smem;
    uint32_t* sBp = (uint32_t*)(smem + 20480);
    const uint32_t sbase = smem_u32(smem);
    const uint32_t sB_base = sbase + 20480;

    uint32_t* Wfc2 = (uint32_t*)(smem + 193536);
    uint32_t* Wfc3 = (uint32_t*)(smem + 211968);
    uint32_t* Wigo = (uint32_t*)(smem + 68608);
    uint32_t* Wfcw = (uint32_t*)(smem + 179200);

    const int tid  = threadIdx.x;
    const int lane = tid & 31;
    const int warp = tid >> 5;
    const int g    = lane >> 2;
    const int t4   = lane & 3;
    const int wr   = warp >> 3;     // 0..1
    const int wc   = warp & 7;      // 0..7

    const size_t rowbase = (size_t)blockIdx.x * 64;
    const float* xg = x + rowbase * 512;

    const int r_ = tid >> 3;
    const int c8 = (tid & 7) << 3;

    float acc[2][8][4];
#pragma unroll
    for (int mi = 0; mi < 2; mi++)
#pragma unroll
        for (int ni = 0; ni < 8; ni++)
#pragma unroll
            for (int e = 0; e < 4; e++) acc[mi][ni][e] = 0.0f;

    float4 av0, av1;

#define LDA(T) do { \
    av0 = *(const float4*)(xg + (size_t)r_ * 512 + (T) * 64 + c8); \
    av1 = *(const float4*)(xg + (size_t)r_ * 512 + (T) * 64 + c8 + 4); \
} while (0)

#define STA(S) do { \
    uint32_t* d_ = sAp + (S) * 2560 + r_ * 40 + ((c8 >> 4) << 3) + ((c8 >> 3) & 1); \
    d_[0] = h2pack(av0.x, av0.y); \
    d_[2] = h2pack(av0.z, av0.w); \
    d_[4] = h2pack(av1.x, av1.y); \
    d_[6] = h2pack(av1.z, av1.w); \
} while (0)

#define CPB_NC(T, S) do { \
    const char* src_ = (const char*)g_WbF + (size_t)(T) * 65536 + tid * 16; \
    uint32_t dst_ = sB_base + (S) * 65536 + tid * 16; \
    _Pragma("unroll") \
    for (int i_ = 0; i_ < 8; i_++) \
        asm volatile("cp.async.cg.shared.global [%0], [%1], 16;" \
                     :: "r"(dst_ + i_ * 8192), "l"(src_ + i_ * 8192)); \
} while (0)

#define FILLW_NC(off_bytes, bytes, dst_off) do { \
    const char* s_ = (const char*)g_WtF + (off_bytes); \
    uint32_t d_ = sbase + (dst_off); \
    for (int o_ = tid * 16; o_ < (bytes); o_ += 8192) \
        asm volatile("cp.async.cg.shared.global [%0], [%1], 16;" \
                     :: "r"(d_ + o_), "l"(s_ + o_)); \
} while (0)

#define CPCOMMIT() asm volatile("cp.async.commit_group;" ::: "memory")
#define CPWAIT(N)  asm volatile("cp.async.wait_group %0;" :: "n"(N) : "memory")

    // ---- prologue ----
    LDA(0);
    CPB_NC(0, 0);
    CPCOMMIT();
    STA(0);
    CPWAIT(0);
    __syncthreads();

    // ---- mainloop: 8 double-buffered k-tiles of 64 ----
#pragma unroll 1
    for (int t = 0; t < 8; t++) {
        const int cur = t & 1, nxt = cur ^ 1;
        if (t < 7) {
            LDA(t + 1);
            CPB_NC(t + 1, nxt);
            if (t == 0) FILLW_NC(0, 18432, 193536);        // fc2
            if (t == 1) FILLW_NC(18432, 20480, 211968);    // fc3
            CPCOMMIT();
        }
#pragma unroll
        for (int step = 0; step < 4; step++) {
            uint2 alo[2], ahi[2];
#pragma unroll
            for (int mi = 0; mi < 2; mi++) {
                const uint32_t* ap = sAp + cur * 2560 +
                    (wr * 32 + mi * 16 + g) * 40 + step * 8 + t4 * 2;
                alo[mi] = *(const uint2*)ap;
                ahi[mi] = *(const uint2*)(ap + 8 * 40);
            }
#pragma unroll
            for (int pi = 0; pi < 4; pi++) {
                uint4 bq = *(const uint4*)(sBp + cur * 16384 +
                    ((step * 32 + wc * 4 + pi) * 32 + lane) * 4);
#pragma unroll
                for (int mi = 0; mi < 2; mi++) {
                    mma16(acc[mi][2 * pi],     alo[mi].x, ahi[mi].x, alo[mi].y, ahi[mi].y, bq.x, bq.y);
                    mma16(acc[mi][2 * pi + 1], alo[mi].x, ahi[mi].x, alo[mi].y, ahi[mi].y, bq.z, bq.w);
                }
            }
        }
        if (t < 7) {
            STA(nxt);
            CPWAIT(0);
        }
        __syncthreads();
    }

    // ======================= tail =======================
    uint32_t* B0  = (uint32_t*)smem;             // 64 x PH  (fp16 data)
    uint32_t* B2H = (uint32_t*)(smem + 18432);   // 64 x PB2 (half2 preacts)

    const int twm = wr;
    const int twn = wc;

    // ---- S0: d1 -> B0 (wc 0,1); gate preacts (half2) -> B2H (wc 2..7) ----
    if (wc < 2) {
#pragma unroll
        for (int mi = 0; mi < 2; mi++)
#pragma unroll
            for (int ni = 0; ni < 8; ni++) {
                int r = wr * 32 + mi * 16 + g;
                int cg = wc * 64 + ni * 8 + t4 * 2;
                int w0 = kword(cg);
                B0[r * PH + w0] = h2pack(fmaxf(acc[mi][ni][0] + fc1_b[cg], 0.f),
                                         fmaxf(acc[mi][ni][1] + fc1_b[cg + 1], 0.f));
                B0[(r + 8) * PH + w0] = h2pack(fmaxf(acc[mi][ni][2] + fc1_b[cg], 0.f),
                                               fmaxf(acc[mi][ni][3] + fc1_b[cg + 1], 0.f));
            }
    } else {
#pragma unroll
        for (int mi = 0; mi < 2; mi++)
#pragma unroll
            for (int ni = 0; ni < 8; ni++)
#pragma unroll
                for (int eh = 0; eh < 2; eh++) {
                    int r = wr * 32 + mi * 16 + g + eh * 8;
                    int cg = wc * 64 + ni * 8 + t4 * 2;
                    int bi0 = (cg < 256) ? cg - 128 : cg;
                    int pc = cg - 128;
                    B2H[r * PB2 + (pc >> 1)] =
                        h2pack(acc[mi][ni][eh * 2]     + b_ih[bi0]     + b_hh[bi0],
                               acc[mi][ni][eh * 2 + 1] + b_ih[bi0 + 1] + b_hh[bi0 + 1]);
                }
    }
    FILLW_NC(38912, 110592, 68608);   // Wigo (9728 words *4 = 38912 B offset)
    CPCOMMIT();
    __syncthreads();

    // ---- G1: d2 = relu(d1 @ fc2.T + b)  [fc2 arrived during mainloop] ----
    {
        float tac1[2][1][4];
#pragma unroll
        for (int mi = 0; mi < 2; mi++)
#pragma unroll
            for (int e = 0; e < 4; e++) tac1[mi][0][e] = 0.f;
        tgemm_h<8, 1, PH, PH>(B0, Wfc2, tac1, twm, twn, g, t4);
        __syncthreads();
        int c = twn * 8 + t4 * 2;
        int w0 = kword(c);
#pragma unroll
        for (int mi = 0; mi < 2; mi++) {
            int r = twm * 32 + mi * 16 + g;
            B0[r * PH + w0] = h2pack(fmaxf(tac1[mi][0][0] + fc2_b[c], 0.f),
                                     fmaxf(tac1[mi][0][1] + fc2_b[c + 1], 0.f));
            B0[(r + 8) * PH + w0] = h2pack(fmaxf(tac1[mi][0][2] + fc2_b[c], 0.f),
                                           fmaxf(tac1[mi][0][3] + fc2_b[c + 1], 0.f));
        }
        __syncthreads();
    }

    // ---- G2: d3 = d2 @ fc3.T + b ----
    {
        float tac2[2][2][4];
#pragma unroll
        for (int mi = 0; mi < 2; mi++)
#pragma unroll
            for (int ni = 0; ni < 2; ni++)
#pragma unroll
                for (int e = 0; e < 4; e++) tac2[mi][ni][e] = 0.f;
        tgemm_h<4, 2, PH, PF3>(B0, Wfc3, tac2, twm, twn, g, t4);
        __syncthreads();
#pragma unroll
        for (int mi = 0; mi < 2; mi++)
#pragma unroll
            for (int ni = 0; ni < 2; ni++) {
                int r = twm * 32 + mi * 16 + g;
                int c = (twn * 2 + ni) * 8 + t4 * 2;
                int w0 = kword(c);
                B0[r * PH + w0] = h2pack(tac2[mi][ni][0] + fc3_b[c],
                                         tac2[mi][ni][1] + fc3_b[c + 1]);
                B0[(r + 8) * PH + w0] = h2pack(tac2[mi][ni][2] + fc3_b[c],
                                               tac2[mi][ni][3] + fc3_b[c + 1]);
            }
        FILLW_NC(149504, 36864, 179200);   // fcw (37376 w *4)
        CPCOMMIT();
        CPWAIT(1);                          // force Wigo complete
        __syncthreads();
    }

    // ---- G3: merged gates: [i|g|o] = d3 @ Wigo.T + preacts -> h (regs) ----
    float hh[2][2][4];
    {
        float tg[2][6][4];
#pragma unroll
        for (int mi = 0; mi < 2; mi++)
#pragma unroll
            for (int ni = 0; ni < 6; ni++)
#pragma unroll
                for (int e = 0; e < 4; e++) tg[mi][ni][e] = 0.f;
        tgemm_h<8, 6, PH, PH>(B0, Wigo, tg, twm, twn, g, t4);
#pragma unroll
        for (int mi = 0; mi < 2; mi++)
#pragma unroll
            for (int ni = 0; ni < 2; ni++)
#pragma unroll
                for (int eh = 0; eh < 2; eh++) {
                    int r = twm * 32 + mi * 16 + g + eh * 8;
                    int wbase = r * PB2 + twn * 8 + ni * 4 + t4;
                    float2 pi_ = __half22float2(*(const __half2*)&B2H[wbase]);
                    float2 pg_ = __half22float2(*(const __half2*)&B2H[wbase + 64]);
                    float2 po_ = __half22float2(*(const __half2*)&B2H[wbase + 128]);
#pragma unroll
                    for (int l = 0; l < 2; l++) {
                        int e = eh * 2 + l;
                        float iv = tg[mi][ni][e]     + (l ? pi_.y : pi_.x);
                        float gv = tg[mi][2 + ni][e] + (l ? pg_.y : pg_.x);
                        float ov = tg[mi][4 + ni][e] + (l ? po_.y : po_.x);
                        float cv = fsigm(iv) * ftanhA(gv);
                        hh[mi][ni][e] = fsigm(ov) * ftanhA(cv);
                    }
                }
    }
    __syncthreads();
#pragma unroll
    for (int mi = 0; mi < 2; mi++)
#pragma unroll
        for (int ni = 0; ni < 2; ni++) {
            int r = twm * 32 + mi * 16 + g;
            int c = (twn * 2 + ni) * 8 + t4 * 2;
            int w0 = kword(c);
            B0[r * PH + w0]       = h2pack(hh[mi][ni][0], hh[mi][ni][1]);
            B0[(r + 8) * PH + w0] = h2pack(hh[mi][ni][2], hh[mi][ni][3]);
        }
    CPWAIT(0);                              // fcw complete
    __syncthreads();

    // ---- G4: out = h @ fc_w.T + fc_b ----
    {
        float tac2[2][2][4];
#pragma unroll
        for (int mi = 0; mi < 2; mi++)
#pragma unroll
            for (int ni = 0; ni < 2; ni++)
#pragma unroll
                for (int e = 0; e < 4; e++) tac2[mi][ni][e] = 0.f;
        tgemm_h<8, 2, PH, PH>(B0, Wfcw, tac2, twm, twn, g, t4);
#pragma unroll
        for (int mi = 0; mi < 2; mi++)
#pragma unroll
            for (int ni = 0; ni < 2; ni++) {
                int r = twm * 32 + mi * 16 + g;
                int c = (twn * 2 + ni) * 8 + t4 * 2;
                *(float2*)(out + (rowbase + r) * 128 + c) =
                    make_float2(tac2[mi][ni][0] + fc_b[c], tac2[mi][ni][1] + fc_b[c + 1]);
                *(float2*)(out + (rowbase + r + 8) * 128 + c) =
                    make_float2(tac2[mi][ni][2] + fc_b[c], tac2[mi][ni][3] + fc_b[c + 1]);
            }
    }
#undef LDA
#undef STA
#undef CPB_NC
#undef FILLW_NC
#undef CPCOMMIT
#undef CPWAIT
}

// ---------------------------------------------------------------------------
extern "C" void kernel_launch(void* const* d_in, const int* in_sizes, int n_in,
                              void* d_out, int out_size) {
    const float* x     = (const float*)d_in[0];
    const float* fc1_w = (const float*)d_in[1];
    const float* fc1_b = (const float*)d_in[2];
    const float* fc2_w = (const float*)d_in[3];
    const float* fc2_b = (const float*)d_in[4];
    const float* fc3_w = (const float*)d_in[5];
    const float* fc3_b = (const float*)d_in[6];
    const float* W_ih  = (const float*)d_in[7];
    // d_in[8] = W_hh (dead: h_prev == 0)
    const float* b_ih  = (const float*)d_in[9];
    const float* b_hh  = (const float*)d_in[10];
    // d_in[11..12] = attn_w, attn_b (dead: softmax over length-1 seq == 1)
    const float* fc_w  = (const float*)d_in[13];
    const float* fc_b  = (const float*)d_in[14];
    float* out = (float*)d_out;

    const int smem = 232448;
    cudaFuncSetAttribute(fused_kernel, cudaFuncAttributeMaxDynamicSharedMemorySize, smem);

    pack_kernel<<<694, 256>>>(fc1_w, fc2_w, fc3_w, W_ih, fc_w);
    fused_kernel<<<NROWS / 64, 512, smem>>>(x, fc1_b, fc2_b, fc3_b,
                                            b_ih, b_hh, fc_b, out);
}